// round 13
// baseline (speedup 1.0000x reference)
#include <cuda_runtime.h>
#include <cuda_fp16.h>
#include <stdint.h>
#include <math.h>

#define TOKENS 8192
#define NSEQ   2048
#define CDIM   1024
#define MLPH   4096
#define NHEADS 16
#define DHEAD  64
#define LN_EPS 1e-5f

#define SLAB 8388608ull
#define WSZ  1048576ull   // 1024*1024
// scratch: 9 slabs + mlp hidden + 6 transposed weights (4*1M + 2*4M)
__device__ float g_scratch[9ull * SLAB + (unsigned long long)TOKENS * MLPH
                           + 4ull * WSZ + 2ull * (unsigned long long)CDIM * MLPH];

// ===========================================================================
// common helpers
// ===========================================================================
__device__ __forceinline__ float4 blockReduce4(float4 v) {
    __shared__ float4 red[8];
    #pragma unroll
    for (int o = 16; o > 0; o >>= 1) {
        v.x += __shfl_xor_sync(0xffffffffu, v.x, o);
        v.y += __shfl_xor_sync(0xffffffffu, v.y, o);
        v.z += __shfl_xor_sync(0xffffffffu, v.z, o);
        v.w += __shfl_xor_sync(0xffffffffu, v.w, o);
    }
    int w = threadIdx.x >> 5;
    if ((threadIdx.x & 31) == 0) red[w] = v;
    __syncthreads();
    v = red[threadIdx.x & 7];
    #pragma unroll
    for (int o = 4; o > 0; o >>= 1) {
        v.x += __shfl_xor_sync(0xffffffffu, v.x, o);
        v.y += __shfl_xor_sync(0xffffffffu, v.y, o);
        v.z += __shfl_xor_sync(0xffffffffu, v.z, o);
        v.w += __shfl_xor_sync(0xffffffffu, v.w, o);
    }
    return v;
}

__device__ __forceinline__ unsigned f2h2(float x, float y) {
    __half2 h = __float22half2_rn(make_float2(x, y));
    return *reinterpret_cast<unsigned*>(&h);
}

// fp16 tensor-core mma: D(f32) += A(f16) * B(f16), m16n8k16, row.col
__device__ __forceinline__ void mma_fp16(float* d, const unsigned* a,
                                         const unsigned* b) {
    asm volatile(
        "mma.sync.aligned.m16n8k16.row.col.f32.f16.f16.f32 "
        "{%0,%1,%2,%3}, {%4,%5,%6,%7}, {%8,%9}, {%0,%1,%2,%3};\n"
        : "+f"(d[0]), "+f"(d[1]), "+f"(d[2]), "+f"(d[3])
        : "r"(a[0]), "r"(a[1]), "r"(a[2]), "r"(a[3]),
          "r"(b[0]), "r"(b[1]));
}

// ===========================================================================
// LayerNorm kernels
// ===========================================================================
__global__ __launch_bounds__(256) void ln_qkv_kernel(
    const float* __restrict__ x, const float* __restrict__ pe,
    const float* __restrict__ nqg, const float* __restrict__ nqb,
    const float* __restrict__ nkg, const float* __restrict__ nkb,
    const float* __restrict__ nvg, const float* __restrict__ nvb,
    float* __restrict__ lnq, float* __restrict__ lnk, float* __restrict__ lnv)
{
    int t = blockIdx.x;
    int n = t & (NSEQ - 1);
    int tid = threadIdx.x;

    const float4* xr = (const float4*)(x + (size_t)t * CDIM);
    const float4* pr = (const float4*)(pe + (size_t)n * CDIM);
    float4 xv = xr[tid];
    float4 pv = pr[tid];
    float4 xp = make_float4(xv.x + pv.x, xv.y + pv.y, xv.z + pv.z, xv.w + pv.w);

    float4 s;
    s.x = xv.x + xv.y + xv.z + xv.w;
    s.y = xv.x * xv.x + xv.y * xv.y + xv.z * xv.z + xv.w * xv.w;
    s.z = xp.x + xp.y + xp.z + xp.w;
    s.w = xp.x * xp.x + xp.y * xp.y + xp.z * xp.z + xp.w * xp.w;
    s = blockReduce4(s);

    const float inv = 1.0f / (float)CDIM;
    float m1 = s.x * inv, v1 = s.y * inv - m1 * m1;
    float r1 = rsqrtf(v1 + LN_EPS);
    float m2 = s.z * inv, v2 = s.w * inv - m2 * m2;
    float r2 = rsqrtf(v2 + LN_EPS);

    float4 g, b, o;
    size_t base = (size_t)t * CDIM;

    g = ((const float4*)nqg)[tid]; b = ((const float4*)nqb)[tid];
    o.x = (xv.x - m1) * r1 * g.x + b.x;
    o.y = (xv.y - m1) * r1 * g.y + b.y;
    o.z = (xv.z - m1) * r1 * g.z + b.z;
    o.w = (xv.w - m1) * r1 * g.w + b.w;
    ((float4*)(lnq + base))[tid] = o;

    float4 nrm;
    nrm.x = (xp.x - m2) * r2; nrm.y = (xp.y - m2) * r2;
    nrm.z = (xp.z - m2) * r2; nrm.w = (xp.w - m2) * r2;

    g = ((const float4*)nkg)[tid]; b = ((const float4*)nkb)[tid];
    o.x = nrm.x * g.x + b.x; o.y = nrm.y * g.y + b.y;
    o.z = nrm.z * g.z + b.z; o.w = nrm.w * g.w + b.w;
    ((float4*)(lnk + base))[tid] = o;

    g = ((const float4*)nvg)[tid]; b = ((const float4*)nvb)[tid];
    o.x = nrm.x * g.x + b.x; o.y = nrm.y * g.y + b.y;
    o.z = nrm.z * g.z + b.z; o.w = nrm.w * g.w + b.w;
    ((float4*)(lnv + base))[tid] = o;
}

__global__ __launch_bounds__(256) void ln_kernel(
    const float* __restrict__ in, const float* __restrict__ gg,
    const float* __restrict__ bb, float* __restrict__ out)
{
    int t = blockIdx.x;
    int tid = threadIdx.x;
    const float4* xr = (const float4*)(in + (size_t)t * CDIM);
    float4 xv = xr[tid];
    float4 s;
    s.x = xv.x + xv.y + xv.z + xv.w;
    s.y = xv.x * xv.x + xv.y * xv.y + xv.z * xv.z + xv.w * xv.w;
    s.z = 0.f; s.w = 0.f;
    s = blockReduce4(s);
    const float inv = 1.0f / (float)CDIM;
    float m = s.x * inv, v = s.y * inv - m * m;
    float r = rsqrtf(v + LN_EPS);
    float4 g = ((const float4*)gg)[tid];
    float4 b = ((const float4*)bb)[tid];
    float4 o;
    o.x = (xv.x - m) * r * g.x + b.x;
    o.y = (xv.y - m) * r * g.y + b.y;
    o.z = (xv.z - m) * r * g.z + b.z;
    o.w = (xv.w - m) * r * g.w + b.w;
    ((float4*)(out + (size_t)t * CDIM))[tid] = o;
}

// ===========================================================================
// weight transpose: W[R][C] -> Wt[C][R]
// ===========================================================================
__global__ __launch_bounds__(256) void transpose_kernel(
    const float* __restrict__ W, float* __restrict__ Wt, int R, int C)
{
    __shared__ float t[32][33];
    int bx = blockIdx.x * 32;   // C offset
    int by = blockIdx.y * 32;   // R offset
    int tx = threadIdx.x & 31, ty4 = (threadIdx.x >> 5) * 4;
    #pragma unroll
    for (int j = 0; j < 4; j++)
        t[ty4 + j][tx] = W[(size_t)(by + ty4 + j) * C + bx + tx];
    __syncthreads();
    #pragma unroll
    for (int j = 0; j < 4; j++)
        Wt[(size_t)(bx + ty4 + j) * R + by + tx] = t[tx][ty4 + j];
}

// ===========================================================================
// fp16 GEMM: Y[M,N] = X[M,K] @ WT[N,K]^T + bias.
// 128x128 tile, BK=32, double-buffered half2 smem, 8 warps (2x4), 64x32/warp,
// m16n8k16 mma, fp32 accum.
// As/Bs layout: [row][k] halves, stride 40 (bank-perfect frag loads).
// EPI: 0 bias ; 1 bias+LeakyReLU ; 2 bias+residual ; 3 bias+transposed store.
// ===========================================================================
#define GASTR 40

template <int EPI>
__global__ __launch_bounds__(256, 2) void gemm_fp16(
    const float* __restrict__ X, const float* __restrict__ WT,
    const float* __restrict__ bias, const float* __restrict__ Res,
    float* __restrict__ Y, int M, int N, int K)
{
    __shared__ __half As[2][128][GASTR];
    __shared__ __half Bs[2][128][GASTR];

    int tid = threadIdx.x;
    int bm = blockIdx.y * 128;
    int bn = blockIdx.x * 128;

    int warp = tid >> 5, lane = tid & 31;
    int wm = (warp & 1) * 64;
    int wn = (warp >> 1) * 32;
    int tg = lane & 3, gid = lane >> 2;

    int lr = tid >> 1;            // staging row 0..127
    int lc = (tid & 1) * 16;      // staging k offset 0 or 16

    float acc[4][4][4];
    #pragma unroll
    for (int i = 0; i < 4; i++)
        #pragma unroll
        for (int j = 0; j < 4; j++)
            #pragma unroll
            for (int r = 0; r < 4; r++) acc[i][j][r] = 0.f;

    const float* Aptr = X + (size_t)(bm + lr) * K + lc;
    const float* Bptr = WT + (size_t)(bn + lr) * K + lc;

    unsigned pa[8], pb[8];
    {
        float4 v0 = *(const float4*)(Aptr);
        float4 v1 = *(const float4*)(Aptr + 4);
        float4 v2 = *(const float4*)(Aptr + 8);
        float4 v3 = *(const float4*)(Aptr + 12);
        pa[0] = f2h2(v0.x, v0.y); pa[1] = f2h2(v0.z, v0.w);
        pa[2] = f2h2(v1.x, v1.y); pa[3] = f2h2(v1.z, v1.w);
        pa[4] = f2h2(v2.x, v2.y); pa[5] = f2h2(v2.z, v2.w);
        pa[6] = f2h2(v3.x, v3.y); pa[7] = f2h2(v3.z, v3.w);
        v0 = *(const float4*)(Bptr);
        v1 = *(const float4*)(Bptr + 4);
        v2 = *(const float4*)(Bptr + 8);
        v3 = *(const float4*)(Bptr + 12);
        pb[0] = f2h2(v0.x, v0.y); pb[1] = f2h2(v0.z, v0.w);
        pb[2] = f2h2(v1.x, v1.y); pb[3] = f2h2(v1.z, v1.w);
        pb[4] = f2h2(v2.x, v2.y); pb[5] = f2h2(v2.z, v2.w);
        pb[6] = f2h2(v3.x, v3.y); pb[7] = f2h2(v3.z, v3.w);
    }
    // stage buffer 0
    *(uint4*)&As[0][lr][lc]     = make_uint4(pa[0], pa[1], pa[2], pa[3]);
    *(uint4*)&As[0][lr][lc + 8] = make_uint4(pa[4], pa[5], pa[6], pa[7]);
    *(uint4*)&Bs[0][lr][lc]     = make_uint4(pb[0], pb[1], pb[2], pb[3]);
    *(uint4*)&Bs[0][lr][lc + 8] = make_uint4(pb[4], pb[5], pb[6], pb[7]);
    __syncthreads();

    for (int k0 = 0; k0 < K; k0 += 32) {
        int cur = (k0 >> 5) & 1;
        int nxt = cur ^ 1;
        bool has_next = (k0 + 32 < K);

        if (has_next) {
            const float* ap = Aptr + k0 + 32;
            const float* bp = Bptr + k0 + 32;
            float4 v0 = *(const float4*)(ap);
            float4 v1 = *(const float4*)(ap + 4);
            float4 v2 = *(const float4*)(ap + 8);
            float4 v3 = *(const float4*)(ap + 12);
            pa[0] = f2h2(v0.x, v0.y); pa[1] = f2h2(v0.z, v0.w);
            pa[2] = f2h2(v1.x, v1.y); pa[3] = f2h2(v1.z, v1.w);
            pa[4] = f2h2(v2.x, v2.y); pa[5] = f2h2(v2.z, v2.w);
            pa[6] = f2h2(v3.x, v3.y); pa[7] = f2h2(v3.z, v3.w);
            v0 = *(const float4*)(bp);
            v1 = *(const float4*)(bp + 4);
            v2 = *(const float4*)(bp + 8);
            v3 = *(const float4*)(bp + 12);
            pb[0] = f2h2(v0.x, v0.y); pb[1] = f2h2(v0.z, v0.w);
            pb[2] = f2h2(v1.x, v1.y); pb[3] = f2h2(v1.z, v1.w);
            pb[4] = f2h2(v2.x, v2.y); pb[5] = f2h2(v2.z, v2.w);
            pb[6] = f2h2(v3.x, v3.y); pb[7] = f2h2(v3.z, v3.w);
        }

        #pragma unroll
        for (int kk = 0; kk < 2; kk++) {
            int kb = kk * 16;
            unsigned af[4][4];
            #pragma unroll
            for (int mi = 0; mi < 4; mi++) {
                int r = wm + mi * 16 + gid;
                af[mi][0] = *(const unsigned*)&As[cur][r][kb + 2 * tg];
                af[mi][1] = *(const unsigned*)&As[cur][r + 8][kb + 2 * tg];
                af[mi][2] = *(const unsigned*)&As[cur][r][kb + 2 * tg + 8];
                af[mi][3] = *(const unsigned*)&As[cur][r + 8][kb + 2 * tg + 8];
            }
            unsigned bf[4][2];
            #pragma unroll
            for (int ni = 0; ni < 4; ni++) {
                int c = wn + ni * 8 + gid;
                bf[ni][0] = *(const unsigned*)&Bs[cur][c][kb + 2 * tg];
                bf[ni][1] = *(const unsigned*)&Bs[cur][c][kb + 2 * tg + 8];
            }
            #pragma unroll
            for (int mi = 0; mi < 4; mi++)
                #pragma unroll
                for (int ni = 0; ni < 4; ni++)
                    mma_fp16(acc[mi][ni], af[mi], bf[ni]);
        }

        if (has_next) {
            *(uint4*)&As[nxt][lr][lc]     = make_uint4(pa[0], pa[1], pa[2], pa[3]);
            *(uint4*)&As[nxt][lr][lc + 8] = make_uint4(pa[4], pa[5], pa[6], pa[7]);
            *(uint4*)&Bs[nxt][lr][lc]     = make_uint4(pb[0], pb[1], pb[2], pb[3]);
            *(uint4*)&Bs[nxt][lr][lc + 8] = make_uint4(pb[4], pb[5], pb[6], pb[7]);
        }
        __syncthreads();
    }

    // ---- epilogue (C frag: rows gid,gid+8; cols 2tg,2tg+1 per n-frag) ----
    if (EPI == 3) {
        #pragma unroll
        for (int mi = 0; mi < 4; mi++) {
            int r0 = bm + wm + mi * 16 + gid;
            int r1 = r0 + 8;
            #pragma unroll
            for (int ni = 0; ni < 4; ni++) {
                int col = bn + wn + ni * 8 + 2 * tg;
                float bs0 = bias[col], bs1 = bias[col + 1];
                Y[(size_t)col * M + r0]       = acc[mi][ni][0] + bs0;
                Y[(size_t)(col + 1) * M + r0] = acc[mi][ni][1] + bs1;
                Y[(size_t)col * M + r1]       = acc[mi][ni][2] + bs0;
                Y[(size_t)(col + 1) * M + r1] = acc[mi][ni][3] + bs1;
            }
        }
        return;
    }

    #pragma unroll
    for (int mi = 0; mi < 4; mi++) {
        int r0 = bm + wm + mi * 16 + gid;
        int r1 = r0 + 8;
        #pragma unroll
        for (int ni = 0; ni < 4; ni++) {
            int col = bn + wn + ni * 8 + 2 * tg;
            float2 bs = *(const float2*)(bias + col);
            float2 v0, v1;
            v0.x = acc[mi][ni][0] + bs.x;
            v0.y = acc[mi][ni][1] + bs.y;
            v1.x = acc[mi][ni][2] + bs.x;
            v1.y = acc[mi][ni][3] + bs.y;
            if (EPI == 1) {
                v0.x = v0.x >= 0.f ? v0.x : 0.1f * v0.x;
                v0.y = v0.y >= 0.f ? v0.y : 0.1f * v0.y;
                v1.x = v1.x >= 0.f ? v1.x : 0.1f * v1.x;
                v1.y = v1.y >= 0.f ? v1.y : 0.1f * v1.y;
            }
            if (EPI == 2) {
                float2 q0 = *(const float2*)(Res + (size_t)r0 * N + col);
                float2 q1 = *(const float2*)(Res + (size_t)r1 * N + col);
                v0.x += q0.x; v0.y += q0.y;
                v1.x += q1.x; v1.y += q1.y;
            }
            *(float2*)(Y + (size_t)r0 * N + col) = v0;
            *(float2*)(Y + (size_t)r1 * N + col) = v1;
        }
    }
}

// ===========================================================================
// Flash-attention v4: fp16 m16n8k16 for S and PV.
// Block = 128 q-tile x one (b,h). 8 warps; warp w owns q rows [16w,16w+16),
// full k=128 per warp. Q,K from [token][C] (d contiguous); V from vT [C][tok].
// smem (halves): Qs[128][72], Ks[128][72], Vs[64][136], Ps[128][136].
// ===========================================================================
#define QS_STR 72
#define VS_STR 136
#define PS_STR 136
#define A4_QH (128 * QS_STR)
#define A4_VH (64 * VS_STR)
#define A4_PH (128 * PS_STR)
#define ATT4_SMEM_BYTES ((2 * A4_QH + A4_VH + A4_PH) * 2)

__global__ __launch_bounds__(256) void attn4_kernel(
    const float* __restrict__ Q, const float* __restrict__ K,
    const float* __restrict__ VT, float* __restrict__ O)
{
    extern __shared__ __half hsm[];
    __half* Qs = hsm;
    __half* Ks = hsm + A4_QH;
    __half* Vs = hsm + 2 * A4_QH;
    __half* Ps = hsm + 2 * A4_QH + A4_VH;

    int qt = blockIdx.x;
    int bh = blockIdx.y;
    int b = bh >> 4, h = bh & 15;

    int tid = threadIdx.x;
    int warp = tid >> 5, lane = tid & 31;
    int gid = lane >> 2, tg = lane & 3;
    int wq = warp * 16;

    const size_t tokbase = (size_t)b * NSEQ;
    const float* qb = Q + (tokbase + (size_t)qt * 128) * CDIM + h * DHEAD;
    const float* kb = K + tokbase * CDIM + h * DHEAD;
    const float* vtb = VT + (size_t)(h * DHEAD) * TOKENS + tokbase;

    const float scale = 0.125f;

    // stage Q [q][d] halves (scaled)
    for (int i = tid; i < 128 * 16; i += 256) {
        int q = i >> 4, c4 = i & 15;
        float4 v = *(const float4*)(qb + (size_t)q * CDIM + c4 * 4);
        *(uint2*)&Qs[q * QS_STR + c4 * 4] =
            make_uint2(f2h2(v.x * scale, v.y * scale),
                       f2h2(v.z * scale, v.w * scale));
    }

    float m0 = -INFINITY, m1 = -INFINITY, l0 = 0.f, l1 = 0.f;
    float o[8][4];
    #pragma unroll
    for (int ni = 0; ni < 8; ni++)
        #pragma unroll
        for (int r = 0; r < 4; r++) o[ni][r] = 0.f;

    for (int kt = 0; kt < NSEQ / 128; kt++) {
        __syncthreads();   // prev PV done reading Vs/Ps; Q staged (first iter)
        // stage K [k][d]
        for (int i = tid; i < 128 * 16; i += 256) {
            int k = i >> 4, c4 = i & 15;
            float4 v = *(const float4*)(kb + (size_t)(kt * 128 + k) * CDIM + c4 * 4);
            *(uint2*)&Ks[k * QS_STR + c4 * 4] =
                make_uint2(f2h2(v.x, v.y), f2h2(v.z, v.w));
        }
        // stage V [d][k] from vT (k contiguous)
        for (int i = tid; i < 64 * 32; i += 256) {
            int d = i >> 5, c = i & 31;
            float4 v = *(const float4*)(vtb + (size_t)d * TOKENS
                                        + (size_t)kt * 128 + c * 4);
            *(uint2*)&Vs[d * VS_STR + c * 4] =
                make_uint2(f2h2(v.x, v.y), f2h2(v.z, v.w));
        }
        __syncthreads();

        // ---- S = Q·K^T : 16 n-frags over d=64 (4 k16 steps) ----
        float s[16][4];
        #pragma unroll
        for (int ni = 0; ni < 16; ni++)
            #pragma unroll
            for (int r = 0; r < 4; r++) s[ni][r] = 0.f;

        #pragma unroll
        for (int d0 = 0; d0 < 64; d0 += 16) {
            unsigned af[4];
            af[0] = *(const unsigned*)&Qs[(wq + gid) * QS_STR + d0 + 2 * tg];
            af[1] = *(const unsigned*)&Qs[(wq + gid + 8) * QS_STR + d0 + 2 * tg];
            af[2] = *(const unsigned*)&Qs[(wq + gid) * QS_STR + d0 + 2 * tg + 8];
            af[3] = *(const unsigned*)&Qs[(wq + gid + 8) * QS_STR + d0 + 2 * tg + 8];
            #pragma unroll
            for (int ni = 0; ni < 16; ni++) {
                unsigned bf[2];
                bf[0] = *(const unsigned*)&Ks[(ni * 8 + gid) * QS_STR + d0 + 2 * tg];
                bf[1] = *(const unsigned*)&Ks[(ni * 8 + gid) * QS_STR + d0 + 2 * tg + 8];
                mma_fp16(s[ni], af, bf);
            }
        }

        // ---- online softmax: thread owns rows gid (c0,c1), gid+8 (c2,c3) ----
        float rm0 = -INFINITY, rm1 = -INFINITY;
        #pragma unroll
        for (int ni = 0; ni < 16; ni++) {
            rm0 = fmaxf(rm0, fmaxf(s[ni][0], s[ni][1]));
            rm1 = fmaxf(rm1, fmaxf(s[ni][2], s[ni][3]));
        }
        rm0 = fmaxf(rm0, __shfl_xor_sync(0xffffffffu, rm0, 1));
        rm0 = fmaxf(rm0, __shfl_xor_sync(0xffffffffu, rm0, 2));
        rm1 = fmaxf(rm1, __shfl_xor_sync(0xffffffffu, rm1, 1));
        rm1 = fmaxf(rm1, __shfl_xor_sync(0xffffffffu, rm1, 2));

        float mn0 = fmaxf(m0, rm0);
        float mn1 = fmaxf(m1, rm1);
        float al0 = __expf(m0 - mn0);
        float al1 = __expf(m1 - mn1);
        m0 = mn0; m1 = mn1;

        float rs0 = 0.f, rs1 = 0.f;
        #pragma unroll
        for (int ni = 0; ni < 16; ni++) {
            s[ni][0] = __expf(s[ni][0] - m0);
            s[ni][1] = __expf(s[ni][1] - m0);
            s[ni][2] = __expf(s[ni][2] - m1);
            s[ni][3] = __expf(s[ni][3] - m1);
            rs0 += s[ni][0] + s[ni][1];
            rs1 += s[ni][2] + s[ni][3];
        }
        rs0 += __shfl_xor_sync(0xffffffffu, rs0, 1);
        rs0 += __shfl_xor_sync(0xffffffffu, rs0, 2);
        rs1 += __shfl_xor_sync(0xffffffffu, rs1, 1);
        rs1 += __shfl_xor_sync(0xffffffffu, rs1, 2);
        l0 = l0 * al0 + rs0;
        l1 = l1 * al1 + rs1;

        #pragma unroll
        for (int ni = 0; ni < 8; ni++) {
            o[ni][0] *= al0; o[ni][1] *= al0;
            o[ni][2] *= al1; o[ni][3] *= al1;
        }

        // ---- store P (half2) into Ps[q][k] (own rows only) ----
        #pragma unroll
        for (int ni = 0; ni < 16; ni++) {
            *(unsigned*)&Ps[(wq + gid) * PS_STR + ni * 8 + 2 * tg] =
                f2h2(s[ni][0], s[ni][1]);
            *(unsigned*)&Ps[(wq + gid + 8) * PS_STR + ni * 8 + 2 * tg] =
                f2h2(s[ni][2], s[ni][3]);
        }
        __syncwarp();   // warp reads only its own 16 rows

        // ---- O += P·V : 8 n-frags (d cols) over k=128 (8 k16 steps) ----
        #pragma unroll
        for (int k0 = 0; k0 < 128; k0 += 16) {
            unsigned af[4];
            af[0] = *(const unsigned*)&Ps[(wq + gid) * PS_STR + k0 + 2 * tg];
            af[1] = *(const unsigned*)&Ps[(wq + gid + 8) * PS_STR + k0 + 2 * tg];
            af[2] = *(const unsigned*)&Ps[(wq + gid) * PS_STR + k0 + 2 * tg + 8];
            af[3] = *(const unsigned*)&Ps[(wq + gid + 8) * PS_STR + k0 + 2 * tg + 8];
            #pragma unroll
            for (int ni = 0; ni < 8; ni++) {
                unsigned bf[2];
                bf[0] = *(const unsigned*)&Vs[(ni * 8 + gid) * VS_STR + k0 + 2 * tg];
                bf[1] = *(const unsigned*)&Vs[(ni * 8 + gid) * VS_STR + k0 + 2 * tg + 8];
                mma_fp16(o[ni], af, bf);
            }
        }
    }

    // ---- normalize + write out ----
    float inv0 = 1.0f / l0;
    float inv1 = 1.0f / l1;
    size_t row0 = tokbase + (size_t)qt * 128 + wq + gid;
    size_t row1 = row0 + 8;
    #pragma unroll
    for (int ni = 0; ni < 8; ni++) {
        int col = h * DHEAD + ni * 8 + 2 * tg;
        *(float2*)(O + row0 * CDIM + col) =
            make_float2(o[ni][0] * inv0, o[ni][1] * inv0);
        *(float2*)(O + row1 * CDIM + col) =
            make_float2(o[ni][2] * inv1, o[ni][3] * inv1);
    }
}

// ===========================================================================
// Launch
// ===========================================================================
extern "C" void kernel_launch(void* const* d_in, const int* in_sizes, int n_in,
                              void* d_out, int out_size)
{
    bool dict_order = (in_sizes[8] == CDIM);

    const float* x   = (const float*)d_in[0];
    const float* pe  = (const float*)d_in[1];
    const float* nqg = (const float*)d_in[2];
    const float* nqb = (const float*)d_in[3];
    const float* nkg = (const float*)d_in[4];
    const float* nkb = (const float*)d_in[5];
    const float* nvg = (const float*)d_in[6];
    const float* nvb = (const float*)d_in[7];

    const float *ng, *nb, *wq, *bq, *wk, *bk, *wv, *bv, *wp, *bp,
                *w1, *b1, *w2, *b2;
    if (dict_order) {
        ng = (const float*)d_in[8];  nb = (const float*)d_in[9];
        wq = (const float*)d_in[10]; bq = (const float*)d_in[11];
        wk = (const float*)d_in[12]; bk = (const float*)d_in[13];
        wv = (const float*)d_in[14]; bv = (const float*)d_in[15];
        wp = (const float*)d_in[16]; bp = (const float*)d_in[17];
        w1 = (const float*)d_in[18]; b1 = (const float*)d_in[19];
        w2 = (const float*)d_in[20]; b2 = (const float*)d_in[21];
    } else {
        wq = (const float*)d_in[8];  bq = (const float*)d_in[9];
        wk = (const float*)d_in[10]; bk = (const float*)d_in[11];
        wv = (const float*)d_in[12]; bv = (const float*)d_in[13];
        wp = (const float*)d_in[14]; bp = (const float*)d_in[15];
        ng = (const float*)d_in[16]; nb = (const float*)d_in[17];
        w1 = (const float*)d_in[18]; b1 = (const float*)d_in[19];
        w2 = (const float*)d_in[20]; b2 = (const float*)d_in[21];
    }
    float* out = (float*)d_out;

    float* sc = nullptr;
    cudaGetSymbolAddress((void**)&sc, g_scratch);
    float* lnq = sc + 0 * SLAB;
    float* lnk = sc + 1 * SLAB;
    float* lnv = sc + 2 * SLAB;
    float* q   = sc + 3 * SLAB;   // [TOKENS][CDIM]
    float* k   = sc + 4 * SLAB;   // [TOKENS][CDIM]
    float* vT  = sc + 5 * SLAB;   // [CDIM][TOKENS]
    float* ao  = sc + 6 * SLAB;
    float* hbuf= sc + 7 * SLAB;
    float* lnh = sc + 8 * SLAB;
    float* m1  = sc + 9 * SLAB;                       // [TOKENS][MLPH]
    float* wqT = m1 + (size_t)TOKENS * MLPH;          // [C][C]
    float* wkT = wqT + WSZ;
    float* wvT = wkT + WSZ;
    float* wpT = wvT + WSZ;
    float* w1T = wpT + WSZ;                           // [MLPH][C]
    float* w2T = w1T + (size_t)CDIM * MLPH;           // [C][MLPH]

    cudaFuncSetAttribute(attn4_kernel,
                         cudaFuncAttributeMaxDynamicSharedMemorySize,
                         ATT4_SMEM_BYTES);

    // 0. transpose weights to [N][K]
    transpose_kernel<<<dim3(CDIM / 32, CDIM / 32), 256>>>(wq, wqT, CDIM, CDIM);
    transpose_kernel<<<dim3(CDIM / 32, CDIM / 32), 256>>>(wk, wkT, CDIM, CDIM);
    transpose_kernel<<<dim3(CDIM / 32, CDIM / 32), 256>>>(wv, wvT, CDIM, CDIM);
    transpose_kernel<<<dim3(CDIM / 32, CDIM / 32), 256>>>(wp, wpT, CDIM, CDIM);
    transpose_kernel<<<dim3(MLPH / 32, CDIM / 32), 256>>>(w1, w1T, CDIM, MLPH);
    transpose_kernel<<<dim3(CDIM / 32, MLPH / 32), 256>>>(w2, w2T, MLPH, CDIM);

    // 1. LayerNorms
    ln_qkv_kernel<<<TOKENS, 256>>>(x, pe, nqg, nqb, nkg, nkb, nvg, nvb,
                                   lnq, lnk, lnv);

    // 2. QKV projections (fp16 tensor cores)
    dim3 gC(CDIM / 128, TOKENS / 128);
    gemm_fp16<0><<<gC, 256>>>(lnq, wqT, bq, nullptr, q, TOKENS, CDIM, CDIM);
    gemm_fp16<0><<<gC, 256>>>(lnk, wkT, bk, nullptr, k, TOKENS, CDIM, CDIM);
    gemm_fp16<3><<<gC, 256>>>(lnv, wvT, bv, nullptr, vT, TOKENS, CDIM, CDIM);

    // 3. Attention
    dim3 gA(NSEQ / 128, 4 * NHEADS);
    attn4_kernel<<<gA, 256, ATT4_SMEM_BYTES>>>(q, k, vT, ao);

    // 4. Output projection + residual
    gemm_fp16<2><<<gC, 256>>>(ao, wpT, bp, x, hbuf, TOKENS, CDIM, CDIM);

    // 5. LN(h)
    ln_kernel<<<TOKENS, 256>>>(hbuf, ng, nb, lnh);

    // 6. MLP1 + LeakyReLU
    dim3 gH(MLPH / 128, TOKENS / 128);
    gemm_fp16<1><<<gH, 256>>>(lnh, w1T, b1, nullptr, m1, TOKENS, MLPH, CDIM);

    // 7. MLP2 + residual -> out
    gemm_fp16<2><<<gC, 256>>>(m1, w2T, b2, hbuf, out, TOKENS, CDIM, MLPH);
}

// round 15
// speedup vs baseline: 1.4562x; 1.4562x over previous
#include <cuda_runtime.h>
#include <cuda_fp16.h>
#include <stdint.h>
#include <math.h>

#define TOKENS 8192
#define NSEQ   2048
#define CDIM   1024
#define MLPH   4096
#define NHEADS 16
#define DHEAD  64
#define LN_EPS 1e-5f

#define SLAB 8388608ull
#define WSZ  1048576ull   // 1024*1024
// scratch: 9 slabs + mlp hidden + 6 transposed weights (4*1M + 2*4M)
__device__ float g_scratch[9ull * SLAB + (unsigned long long)TOKENS * MLPH
                           + 4ull * WSZ + 2ull * (unsigned long long)CDIM * MLPH];

// ===========================================================================
// common helpers
// ===========================================================================
__device__ __forceinline__ float4 blockReduce4(float4 v) {
    __shared__ float4 red[8];
    #pragma unroll
    for (int o = 16; o > 0; o >>= 1) {
        v.x += __shfl_xor_sync(0xffffffffu, v.x, o);
        v.y += __shfl_xor_sync(0xffffffffu, v.y, o);
        v.z += __shfl_xor_sync(0xffffffffu, v.z, o);
        v.w += __shfl_xor_sync(0xffffffffu, v.w, o);
    }
    int w = threadIdx.x >> 5;
    if ((threadIdx.x & 31) == 0) red[w] = v;
    __syncthreads();
    v = red[threadIdx.x & 7];
    #pragma unroll
    for (int o = 4; o > 0; o >>= 1) {
        v.x += __shfl_xor_sync(0xffffffffu, v.x, o);
        v.y += __shfl_xor_sync(0xffffffffu, v.y, o);
        v.z += __shfl_xor_sync(0xffffffffu, v.z, o);
        v.w += __shfl_xor_sync(0xffffffffu, v.w, o);
    }
    return v;
}

__device__ __forceinline__ unsigned f2h2(float x, float y) {
    __half2 h = __float22half2_rn(make_float2(x, y));
    return *reinterpret_cast<unsigned*>(&h);
}

// fp16 tensor-core mma: D(f32) += A(f16) * B(f16), m16n8k16, row.col
__device__ __forceinline__ void mma_fp16(float* d, const unsigned* a,
                                         const unsigned* b) {
    asm volatile(
        "mma.sync.aligned.m16n8k16.row.col.f32.f16.f16.f32 "
        "{%0,%1,%2,%3}, {%4,%5,%6,%7}, {%8,%9}, {%0,%1,%2,%3};\n"
        : "+f"(d[0]), "+f"(d[1]), "+f"(d[2]), "+f"(d[3])
        : "r"(a[0]), "r"(a[1]), "r"(a[2]), "r"(a[3]),
          "r"(b[0]), "r"(b[1]));
}

// ===========================================================================
// LayerNorm kernels
// ===========================================================================
__global__ __launch_bounds__(256) void ln_qkv_kernel(
    const float* __restrict__ x, const float* __restrict__ pe,
    const float* __restrict__ nqg, const float* __restrict__ nqb,
    const float* __restrict__ nkg, const float* __restrict__ nkb,
    const float* __restrict__ nvg, const float* __restrict__ nvb,
    float* __restrict__ lnq, float* __restrict__ lnk, float* __restrict__ lnv)
{
    int t = blockIdx.x;
    int n = t & (NSEQ - 1);
    int tid = threadIdx.x;

    const float4* xr = (const float4*)(x + (size_t)t * CDIM);
    const float4* pr = (const float4*)(pe + (size_t)n * CDIM);
    float4 xv = xr[tid];
    float4 pv = pr[tid];
    float4 xp = make_float4(xv.x + pv.x, xv.y + pv.y, xv.z + pv.z, xv.w + pv.w);

    float4 s;
    s.x = xv.x + xv.y + xv.z + xv.w;
    s.y = xv.x * xv.x + xv.y * xv.y + xv.z * xv.z + xv.w * xv.w;
    s.z = xp.x + xp.y + xp.z + xp.w;
    s.w = xp.x * xp.x + xp.y * xp.y + xp.z * xp.z + xp.w * xp.w;
    s = blockReduce4(s);

    const float inv = 1.0f / (float)CDIM;
    float m1 = s.x * inv, v1 = s.y * inv - m1 * m1;
    float r1 = rsqrtf(v1 + LN_EPS);
    float m2 = s.z * inv, v2 = s.w * inv - m2 * m2;
    float r2 = rsqrtf(v2 + LN_EPS);

    float4 g, b, o;
    size_t base = (size_t)t * CDIM;

    g = ((const float4*)nqg)[tid]; b = ((const float4*)nqb)[tid];
    o.x = (xv.x - m1) * r1 * g.x + b.x;
    o.y = (xv.y - m1) * r1 * g.y + b.y;
    o.z = (xv.z - m1) * r1 * g.z + b.z;
    o.w = (xv.w - m1) * r1 * g.w + b.w;
    ((float4*)(lnq + base))[tid] = o;

    float4 nrm;
    nrm.x = (xp.x - m2) * r2; nrm.y = (xp.y - m2) * r2;
    nrm.z = (xp.z - m2) * r2; nrm.w = (xp.w - m2) * r2;

    g = ((const float4*)nkg)[tid]; b = ((const float4*)nkb)[tid];
    o.x = nrm.x * g.x + b.x; o.y = nrm.y * g.y + b.y;
    o.z = nrm.z * g.z + b.z; o.w = nrm.w * g.w + b.w;
    ((float4*)(lnk + base))[tid] = o;

    g = ((const float4*)nvg)[tid]; b = ((const float4*)nvb)[tid];
    o.x = nrm.x * g.x + b.x; o.y = nrm.y * g.y + b.y;
    o.z = nrm.z * g.z + b.z; o.w = nrm.w * g.w + b.w;
    ((float4*)(lnv + base))[tid] = o;
}

__global__ __launch_bounds__(256) void ln_kernel(
    const float* __restrict__ in, const float* __restrict__ gg,
    const float* __restrict__ bb, float* __restrict__ out)
{
    int t = blockIdx.x;
    int tid = threadIdx.x;
    const float4* xr = (const float4*)(in + (size_t)t * CDIM);
    float4 xv = xr[tid];
    float4 s;
    s.x = xv.x + xv.y + xv.z + xv.w;
    s.y = xv.x * xv.x + xv.y * xv.y + xv.z * xv.z + xv.w * xv.w;
    s.z = 0.f; s.w = 0.f;
    s = blockReduce4(s);
    const float inv = 1.0f / (float)CDIM;
    float m = s.x * inv, v = s.y * inv - m * m;
    float r = rsqrtf(v + LN_EPS);
    float4 g = ((const float4*)gg)[tid];
    float4 b = ((const float4*)bb)[tid];
    float4 o;
    o.x = (xv.x - m) * r * g.x + b.x;
    o.y = (xv.y - m) * r * g.y + b.y;
    o.z = (xv.z - m) * r * g.z + b.z;
    o.w = (xv.w - m) * r * g.w + b.w;
    ((float4*)(out + (size_t)t * CDIM))[tid] = o;
}

// ===========================================================================
// weight transpose: W[R][C] -> Wt[C][R]
// ===========================================================================
__global__ __launch_bounds__(256) void transpose_kernel(
    const float* __restrict__ W, float* __restrict__ Wt, int R, int C)
{
    __shared__ float t[32][33];
    int bx = blockIdx.x * 32;   // C offset
    int by = blockIdx.y * 32;   // R offset
    int tx = threadIdx.x & 31, ty4 = (threadIdx.x >> 5) * 4;
    #pragma unroll
    for (int j = 0; j < 4; j++)
        t[ty4 + j][tx] = W[(size_t)(by + ty4 + j) * C + bx + tx];
    __syncthreads();
    #pragma unroll
    for (int j = 0; j < 4; j++)
        Wt[(size_t)(bx + ty4 + j) * R + by + tx] = t[tx][ty4 + j];
}

// ===========================================================================
// fp16 GEMM: Y[M,N] = X[M,K] @ WT[N,K]^T + bias.
// 128x128 tile, BK=32, double-buffered half2 smem, 8 warps (2x4), 64x32/warp,
// m16n8k16 mma, fp32 accum. NO min-blocks bound (avoid reg-cap spills).
// As/Bs layout: [row][k] halves, stride 40 (bank-perfect frag loads).
// EPI: 0 bias ; 1 bias+LeakyReLU ; 2 bias+residual ; 3 bias+transposed store.
// ===========================================================================
#define GASTR 40

template <int EPI>
__global__ __launch_bounds__(256) void gemm_fp16(
    const float* __restrict__ X, const float* __restrict__ WT,
    const float* __restrict__ bias, const float* __restrict__ Res,
    float* __restrict__ Y, int M, int N, int K)
{
    __shared__ __half As[2][128][GASTR];
    __shared__ __half Bs[2][128][GASTR];

    int tid = threadIdx.x;
    int bm = blockIdx.y * 128;
    int bn = blockIdx.x * 128;

    int warp = tid >> 5, lane = tid & 31;
    int wm = (warp & 1) * 64;
    int wn = (warp >> 1) * 32;
    int tg = lane & 3, gid = lane >> 2;

    int lr = tid >> 1;            // staging row 0..127
    int lc = (tid & 1) * 16;      // staging k offset 0 or 16

    float acc[4][4][4];
    #pragma unroll
    for (int i = 0; i < 4; i++)
        #pragma unroll
        for (int j = 0; j < 4; j++)
            #pragma unroll
            for (int r = 0; r < 4; r++) acc[i][j][r] = 0.f;

    const float* Aptr = X + (size_t)(bm + lr) * K + lc;
    const float* Bptr = WT + (size_t)(bn + lr) * K + lc;

    unsigned pa[8], pb[8];
    {
        float4 v0 = *(const float4*)(Aptr);
        float4 v1 = *(const float4*)(Aptr + 4);
        float4 v2 = *(const float4*)(Aptr + 8);
        float4 v3 = *(const float4*)(Aptr + 12);
        pa[0] = f2h2(v0.x, v0.y); pa[1] = f2h2(v0.z, v0.w);
        pa[2] = f2h2(v1.x, v1.y); pa[3] = f2h2(v1.z, v1.w);
        pa[4] = f2h2(v2.x, v2.y); pa[5] = f2h2(v2.z, v2.w);
        pa[6] = f2h2(v3.x, v3.y); pa[7] = f2h2(v3.z, v3.w);
        v0 = *(const float4*)(Bptr);
        v1 = *(const float4*)(Bptr + 4);
        v2 = *(const float4*)(Bptr + 8);
        v3 = *(const float4*)(Bptr + 12);
        pb[0] = f2h2(v0.x, v0.y); pb[1] = f2h2(v0.z, v0.w);
        pb[2] = f2h2(v1.x, v1.y); pb[3] = f2h2(v1.z, v1.w);
        pb[4] = f2h2(v2.x, v2.y); pb[5] = f2h2(v2.z, v2.w);
        pb[6] = f2h2(v3.x, v3.y); pb[7] = f2h2(v3.z, v3.w);
    }
    // stage buffer 0
    *(uint4*)&As[0][lr][lc]     = make_uint4(pa[0], pa[1], pa[2], pa[3]);
    *(uint4*)&As[0][lr][lc + 8] = make_uint4(pa[4], pa[5], pa[6], pa[7]);
    *(uint4*)&Bs[0][lr][lc]     = make_uint4(pb[0], pb[1], pb[2], pb[3]);
    *(uint4*)&Bs[0][lr][lc + 8] = make_uint4(pb[4], pb[5], pb[6], pb[7]);
    __syncthreads();

    for (int k0 = 0; k0 < K; k0 += 32) {
        int cur = (k0 >> 5) & 1;
        int nxt = cur ^ 1;
        bool has_next = (k0 + 32 < K);

        if (has_next) {
            const float* ap = Aptr + k0 + 32;
            const float* bp = Bptr + k0 + 32;
            float4 v0 = *(const float4*)(ap);
            float4 v1 = *(const float4*)(ap + 4);
            float4 v2 = *(const float4*)(ap + 8);
            float4 v3 = *(const float4*)(ap + 12);
            pa[0] = f2h2(v0.x, v0.y); pa[1] = f2h2(v0.z, v0.w);
            pa[2] = f2h2(v1.x, v1.y); pa[3] = f2h2(v1.z, v1.w);
            pa[4] = f2h2(v2.x, v2.y); pa[5] = f2h2(v2.z, v2.w);
            pa[6] = f2h2(v3.x, v3.y); pa[7] = f2h2(v3.z, v3.w);
            v0 = *(const float4*)(bp);
            v1 = *(const float4*)(bp + 4);
            v2 = *(const float4*)(bp + 8);
            v3 = *(const float4*)(bp + 12);
            pb[0] = f2h2(v0.x, v0.y); pb[1] = f2h2(v0.z, v0.w);
            pb[2] = f2h2(v1.x, v1.y); pb[3] = f2h2(v1.z, v1.w);
            pb[4] = f2h2(v2.x, v2.y); pb[5] = f2h2(v2.z, v2.w);
            pb[6] = f2h2(v3.x, v3.y); pb[7] = f2h2(v3.z, v3.w);
        }

        #pragma unroll
        for (int kk = 0; kk < 2; kk++) {
            int kb = kk * 16;
            unsigned af[4][4];
            #pragma unroll
            for (int mi = 0; mi < 4; mi++) {
                int r = wm + mi * 16 + gid;
                af[mi][0] = *(const unsigned*)&As[cur][r][kb + 2 * tg];
                af[mi][1] = *(const unsigned*)&As[cur][r + 8][kb + 2 * tg];
                af[mi][2] = *(const unsigned*)&As[cur][r][kb + 2 * tg + 8];
                af[mi][3] = *(const unsigned*)&As[cur][r + 8][kb + 2 * tg + 8];
            }
            unsigned bf[4][2];
            #pragma unroll
            for (int ni = 0; ni < 4; ni++) {
                int c = wn + ni * 8 + gid;
                bf[ni][0] = *(const unsigned*)&Bs[cur][c][kb + 2 * tg];
                bf[ni][1] = *(const unsigned*)&Bs[cur][c][kb + 2 * tg + 8];
            }
            #pragma unroll
            for (int mi = 0; mi < 4; mi++)
                #pragma unroll
                for (int ni = 0; ni < 4; ni++)
                    mma_fp16(acc[mi][ni], af[mi], bf[ni]);
        }

        if (has_next) {
            *(uint4*)&As[nxt][lr][lc]     = make_uint4(pa[0], pa[1], pa[2], pa[3]);
            *(uint4*)&As[nxt][lr][lc + 8] = make_uint4(pa[4], pa[5], pa[6], pa[7]);
            *(uint4*)&Bs[nxt][lr][lc]     = make_uint4(pb[0], pb[1], pb[2], pb[3]);
            *(uint4*)&Bs[nxt][lr][lc + 8] = make_uint4(pb[4], pb[5], pb[6], pb[7]);
        }
        __syncthreads();
    }

    // ---- epilogue (C frag: rows gid,gid+8; cols 2tg,2tg+1 per n-frag) ----
    if (EPI == 3) {
        #pragma unroll
        for (int mi = 0; mi < 4; mi++) {
            int r0 = bm + wm + mi * 16 + gid;
            int r1 = r0 + 8;
            #pragma unroll
            for (int ni = 0; ni < 4; ni++) {
                int col = bn + wn + ni * 8 + 2 * tg;
                float bs0 = bias[col], bs1 = bias[col + 1];
                Y[(size_t)col * M + r0]       = acc[mi][ni][0] + bs0;
                Y[(size_t)(col + 1) * M + r0] = acc[mi][ni][1] + bs1;
                Y[(size_t)col * M + r1]       = acc[mi][ni][2] + bs0;
                Y[(size_t)(col + 1) * M + r1] = acc[mi][ni][3] + bs1;
            }
        }
        return;
    }

    #pragma unroll
    for (int mi = 0; mi < 4; mi++) {
        int r0 = bm + wm + mi * 16 + gid;
        int r1 = r0 + 8;
        #pragma unroll
        for (int ni = 0; ni < 4; ni++) {
            int col = bn + wn + ni * 8 + 2 * tg;
            float2 bs = *(const float2*)(bias + col);
            float2 v0, v1;
            v0.x = acc[mi][ni][0] + bs.x;
            v0.y = acc[mi][ni][1] + bs.y;
            v1.x = acc[mi][ni][2] + bs.x;
            v1.y = acc[mi][ni][3] + bs.y;
            if (EPI == 1) {
                v0.x = v0.x >= 0.f ? v0.x : 0.1f * v0.x;
                v0.y = v0.y >= 0.f ? v0.y : 0.1f * v0.y;
                v1.x = v1.x >= 0.f ? v1.x : 0.1f * v1.x;
                v1.y = v1.y >= 0.f ? v1.y : 0.1f * v1.y;
            }
            if (EPI == 2) {
                float2 q0 = *(const float2*)(Res + (size_t)r0 * N + col);
                float2 q1 = *(const float2*)(Res + (size_t)r1 * N + col);
                v0.x += q0.x; v0.y += q0.y;
                v1.x += q1.x; v1.y += q1.y;
            }
            *(float2*)(Y + (size_t)r0 * N + col) = v0;
            *(float2*)(Y + (size_t)r1 * N + col) = v1;
        }
    }
}

// ===========================================================================
// Flash-attention v4: fp16 m16n8k16 for S and PV (unchanged from round 13).
// ===========================================================================
#define QS_STR 72
#define VS_STR 136
#define PS_STR 136
#define A4_QH (128 * QS_STR)
#define A4_VH (64 * VS_STR)
#define A4_PH (128 * PS_STR)
#define ATT4_SMEM_BYTES ((2 * A4_QH + A4_VH + A4_PH) * 2)

__global__ __launch_bounds__(256) void attn4_kernel(
    const float* __restrict__ Q, const float* __restrict__ K,
    const float* __restrict__ VT, float* __restrict__ O)
{
    extern __shared__ __half hsm[];
    __half* Qs = hsm;
    __half* Ks = hsm + A4_QH;
    __half* Vs = hsm + 2 * A4_QH;
    __half* Ps = hsm + 2 * A4_QH + A4_VH;

    int qt = blockIdx.x;
    int bh = blockIdx.y;
    int b = bh >> 4, h = bh & 15;

    int tid = threadIdx.x;
    int warp = tid >> 5, lane = tid & 31;
    int gid = lane >> 2, tg = lane & 3;
    int wq = warp * 16;

    const size_t tokbase = (size_t)b * NSEQ;
    const float* qb = Q + (tokbase + (size_t)qt * 128) * CDIM + h * DHEAD;
    const float* kb = K + tokbase * CDIM + h * DHEAD;
    const float* vtb = VT + (size_t)(h * DHEAD) * TOKENS + tokbase;

    const float scale = 0.125f;

    // stage Q [q][d] halves (scaled)
    for (int i = tid; i < 128 * 16; i += 256) {
        int q = i >> 4, c4 = i & 15;
        float4 v = *(const float4*)(qb + (size_t)q * CDIM + c4 * 4);
        *(uint2*)&Qs[q * QS_STR + c4 * 4] =
            make_uint2(f2h2(v.x * scale, v.y * scale),
                       f2h2(v.z * scale, v.w * scale));
    }

    float m0 = -INFINITY, m1 = -INFINITY, l0 = 0.f, l1 = 0.f;
    float o[8][4];
    #pragma unroll
    for (int ni = 0; ni < 8; ni++)
        #pragma unroll
        for (int r = 0; r < 4; r++) o[ni][r] = 0.f;

    for (int kt = 0; kt < NSEQ / 128; kt++) {
        __syncthreads();   // prev PV done reading Vs/Ps; Q staged (first iter)
        // stage K [k][d]
        for (int i = tid; i < 128 * 16; i += 256) {
            int k = i >> 4, c4 = i & 15;
            float4 v = *(const float4*)(kb + (size_t)(kt * 128 + k) * CDIM + c4 * 4);
            *(uint2*)&Ks[k * QS_STR + c4 * 4] =
                make_uint2(f2h2(v.x, v.y), f2h2(v.z, v.w));
        }
        // stage V [d][k] from vT (k contiguous)
        for (int i = tid; i < 64 * 32; i += 256) {
            int d = i >> 5, c = i & 31;
            float4 v = *(const float4*)(vtb + (size_t)d * TOKENS
                                        + (size_t)kt * 128 + c * 4);
            *(uint2*)&Vs[d * VS_STR + c * 4] =
                make_uint2(f2h2(v.x, v.y), f2h2(v.z, v.w));
        }
        __syncthreads();

        // ---- S = Q·K^T : 16 n-frags over d=64 (4 k16 steps) ----
        float s[16][4];
        #pragma unroll
        for (int ni = 0; ni < 16; ni++)
            #pragma unroll
            for (int r = 0; r < 4; r++) s[ni][r] = 0.f;

        #pragma unroll
        for (int d0 = 0; d0 < 64; d0 += 16) {
            unsigned af[4];
            af[0] = *(const unsigned*)&Qs[(wq + gid) * QS_STR + d0 + 2 * tg];
            af[1] = *(const unsigned*)&Qs[(wq + gid + 8) * QS_STR + d0 + 2 * tg];
            af[2] = *(const unsigned*)&Qs[(wq + gid) * QS_STR + d0 + 2 * tg + 8];
            af[3] = *(const unsigned*)&Qs[(wq + gid + 8) * QS_STR + d0 + 2 * tg + 8];
            #pragma unroll
            for (int ni = 0; ni < 16; ni++) {
                unsigned bf[2];
                bf[0] = *(const unsigned*)&Ks[(ni * 8 + gid) * QS_STR + d0 + 2 * tg];
                bf[1] = *(const unsigned*)&Ks[(ni * 8 + gid) * QS_STR + d0 + 2 * tg + 8];
                mma_fp16(s[ni], af, bf);
            }
        }

        // ---- online softmax: thread owns rows gid (c0,c1), gid+8 (c2,c3) ----
        float rm0 = -INFINITY, rm1 = -INFINITY;
        #pragma unroll
        for (int ni = 0; ni < 16; ni++) {
            rm0 = fmaxf(rm0, fmaxf(s[ni][0], s[ni][1]));
            rm1 = fmaxf(rm1, fmaxf(s[ni][2], s[ni][3]));
        }
        rm0 = fmaxf(rm0, __shfl_xor_sync(0xffffffffu, rm0, 1));
        rm0 = fmaxf(rm0, __shfl_xor_sync(0xffffffffu, rm0, 2));
        rm1 = fmaxf(rm1, __shfl_xor_sync(0xffffffffu, rm1, 1));
        rm1 = fmaxf(rm1, __shfl_xor_sync(0xffffffffu, rm1, 2));

        float mn0 = fmaxf(m0, rm0);
        float mn1 = fmaxf(m1, rm1);
        float al0 = __expf(m0 - mn0);
        float al1 = __expf(m1 - mn1);
        m0 = mn0; m1 = mn1;

        float rs0 = 0.f, rs1 = 0.f;
        #pragma unroll
        for (int ni = 0; ni < 16; ni++) {
            s[ni][0] = __expf(s[ni][0] - m0);
            s[ni][1] = __expf(s[ni][1] - m0);
            s[ni][2] = __expf(s[ni][2] - m1);
            s[ni][3] = __expf(s[ni][3] - m1);
            rs0 += s[ni][0] + s[ni][1];
            rs1 += s[ni][2] + s[ni][3];
        }
        rs0 += __shfl_xor_sync(0xffffffffu, rs0, 1);
        rs0 += __shfl_xor_sync(0xffffffffu, rs0, 2);
        rs1 += __shfl_xor_sync(0xffffffffu, rs1, 1);
        rs1 += __shfl_xor_sync(0xffffffffu, rs1, 2);
        l0 = l0 * al0 + rs0;
        l1 = l1 * al1 + rs1;

        #pragma unroll
        for (int ni = 0; ni < 8; ni++) {
            o[ni][0] *= al0; o[ni][1] *= al0;
            o[ni][2] *= al1; o[ni][3] *= al1;
        }

        // ---- store P (half2) into Ps[q][k] (own rows only) ----
        #pragma unroll
        for (int ni = 0; ni < 16; ni++) {
            *(unsigned*)&Ps[(wq + gid) * PS_STR + ni * 8 + 2 * tg] =
                f2h2(s[ni][0], s[ni][1]);
            *(unsigned*)&Ps[(wq + gid + 8) * PS_STR + ni * 8 + 2 * tg] =
                f2h2(s[ni][2], s[ni][3]);
        }
        __syncwarp();   // warp reads only its own 16 rows

        // ---- O += P·V : 8 n-frags (d cols) over k=128 (8 k16 steps) ----
        #pragma unroll
        for (int k0 = 0; k0 < 128; k0 += 16) {
            unsigned af[4];
            af[0] = *(const unsigned*)&Ps[(wq + gid) * PS_STR + k0 + 2 * tg];
            af[1] = *(const unsigned*)&Ps[(wq + gid + 8) * PS_STR + k0 + 2 * tg];
            af[2] = *(const unsigned*)&Ps[(wq + gid) * PS_STR + k0 + 2 * tg + 8];
            af[3] = *(const unsigned*)&Ps[(wq + gid + 8) * PS_STR + k0 + 2 * tg + 8];
            #pragma unroll
            for (int ni = 0; ni < 8; ni++) {
                unsigned bf[2];
                bf[0] = *(const unsigned*)&Vs[(ni * 8 + gid) * VS_STR + k0 + 2 * tg];
                bf[1] = *(const unsigned*)&Vs[(ni * 8 + gid) * VS_STR + k0 + 2 * tg + 8];
                mma_fp16(o[ni], af, bf);
            }
        }
    }

    // ---- normalize + write out ----
    float inv0 = 1.0f / l0;
    float inv1 = 1.0f / l1;
    size_t row0 = tokbase + (size_t)qt * 128 + wq + gid;
    size_t row1 = row0 + 8;
    #pragma unroll
    for (int ni = 0; ni < 8; ni++) {
        int col = h * DHEAD + ni * 8 + 2 * tg;
        *(float2*)(O + row0 * CDIM + col) =
            make_float2(o[ni][0] * inv0, o[ni][1] * inv0);
        *(float2*)(O + row1 * CDIM + col) =
            make_float2(o[ni][2] * inv1, o[ni][3] * inv1);
    }
}

// ===========================================================================
// Launch
// ===========================================================================
extern "C" void kernel_launch(void* const* d_in, const int* in_sizes, int n_in,
                              void* d_out, int out_size)
{
    bool dict_order = (in_sizes[8] == CDIM);

    const float* x   = (const float*)d_in[0];
    const float* pe  = (const float*)d_in[1];
    const float* nqg = (const float*)d_in[2];
    const float* nqb = (const float*)d_in[3];
    const float* nkg = (const float*)d_in[4];
    const float* nkb = (const float*)d_in[5];
    const float* nvg = (const float*)d_in[6];
    const float* nvb = (const float*)d_in[7];

    const float *ng, *nb, *wq, *bq, *wk, *bk, *wv, *bv, *wp, *bp,
                *w1, *b1, *w2, *b2;
    if (dict_order) {
        ng = (const float*)d_in[8];  nb = (const float*)d_in[9];
        wq = (const float*)d_in[10]; bq = (const float*)d_in[11];
        wk = (const float*)d_in[12]; bk = (const float*)d_in[13];
        wv = (const float*)d_in[14]; bv = (const float*)d_in[15];
        wp = (const float*)d_in[16]; bp = (const float*)d_in[17];
        w1 = (const float*)d_in[18]; b1 = (const float*)d_in[19];
        w2 = (const float*)d_in[20]; b2 = (const float*)d_in[21];
    } else {
        wq = (const float*)d_in[8];  bq = (const float*)d_in[9];
        wk = (const float*)d_in[10]; bk = (const float*)d_in[11];
        wv = (const float*)d_in[12]; bv = (const float*)d_in[13];
        wp = (const float*)d_in[14]; bp = (const float*)d_in[15];
        ng = (const float*)d_in[16]; nb = (const float*)d_in[17];
        w1 = (const float*)d_in[18]; b1 = (const float*)d_in[19];
        w2 = (const float*)d_in[20]; b2 = (const float*)d_in[21];
    }
    float* out = (float*)d_out;

    float* sc = nullptr;
    cudaGetSymbolAddress((void**)&sc, g_scratch);
    float* lnq = sc + 0 * SLAB;
    float* lnk = sc + 1 * SLAB;
    float* lnv = sc + 2 * SLAB;
    float* q   = sc + 3 * SLAB;   // [TOKENS][CDIM]
    float* k   = sc + 4 * SLAB;   // [TOKENS][CDIM]
    float* vT  = sc + 5 * SLAB;   // [CDIM][TOKENS]
    float* ao  = sc + 6 * SLAB;
    float* hbuf= sc + 7 * SLAB;
    float* lnh = sc + 8 * SLAB;
    float* m1  = sc + 9 * SLAB;                       // [TOKENS][MLPH]
    float* wqT = m1 + (size_t)TOKENS * MLPH;          // [C][C]
    float* wkT = wqT + WSZ;
    float* wvT = wkT + WSZ;
    float* wpT = wvT + WSZ;
    float* w1T = wpT + WSZ;                           // [MLPH][C]
    float* w2T = w1T + (size_t)CDIM * MLPH;           // [C][MLPH]

    cudaFuncSetAttribute(attn4_kernel,
                         cudaFuncAttributeMaxDynamicSharedMemorySize,
                         ATT4_SMEM_BYTES);

    // launch order arranged so ncu's -s 5 profiles the first fp16 GEMM:
    // 0:t_wq 1:t_wk 2:t_wv 3:ln_qkv 4:t_wp 5:gemm_q ...
    transpose_kernel<<<dim3(CDIM / 32, CDIM / 32), 256>>>(wq, wqT, CDIM, CDIM);
    transpose_kernel<<<dim3(CDIM / 32, CDIM / 32), 256>>>(wk, wkT, CDIM, CDIM);
    transpose_kernel<<<dim3(CDIM / 32, CDIM / 32), 256>>>(wv, wvT, CDIM, CDIM);

    ln_qkv_kernel<<<TOKENS, 256>>>(x, pe, nqg, nqb, nkg, nkb, nvg, nvb,
                                   lnq, lnk, lnv);

    transpose_kernel<<<dim3(CDIM / 32, CDIM / 32), 256>>>(wp, wpT, CDIM, CDIM);

    // 2. QKV projections (fp16 tensor cores)
    dim3 gC(CDIM / 128, TOKENS / 128);
    gemm_fp16<0><<<gC, 256>>>(lnq, wqT, bq, nullptr, q, TOKENS, CDIM, CDIM);
    gemm_fp16<0><<<gC, 256>>>(lnk, wkT, bk, nullptr, k, TOKENS, CDIM, CDIM);
    gemm_fp16<3><<<gC, 256>>>(lnv, wvT, bv, nullptr, vT, TOKENS, CDIM, CDIM);

    transpose_kernel<<<dim3(MLPH / 32, CDIM / 32), 256>>>(w1, w1T, CDIM, MLPH);
    transpose_kernel<<<dim3(CDIM / 32, MLPH / 32), 256>>>(w2, w2T, MLPH, CDIM);

    // 3. Attention
    dim3 gA(NSEQ / 128, 4 * NHEADS);
    attn4_kernel<<<gA, 256, ATT4_SMEM_BYTES>>>(q, k, vT, ao);

    // 4. Output projection + residual
    gemm_fp16<2><<<gC, 256>>>(ao, wpT, bp, x, hbuf, TOKENS, CDIM, CDIM);

    // 5. LN(h)
    ln_kernel<<<TOKENS, 256>>>(hbuf, ng, nb, lnh);

    // 6. MLP1 + LeakyReLU
    dim3 gH(MLPH / 128, TOKENS / 128);
    gemm_fp16<1><<<gH, 256>>>(lnh, w1T, b1, nullptr, m1, TOKENS, MLPH, CDIM);

    // 7. MLP2 + residual -> out
    gemm_fp16<2><<<gC, 256>>>(m1, w2T, b2, hbuf, out, TOKENS, CDIM, MLPH);
}

// round 16
// speedup vs baseline: 1.6629x; 1.1419x over previous
#include <cuda_runtime.h>
#include <cuda_fp16.h>
#include <stdint.h>
#include <math.h>

#define TOKENS 8192
#define NSEQ   2048
#define CDIM   1024
#define MLPH   4096
#define NHEADS 16
#define DHEAD  64
#define LN_EPS 1e-5f

#define SLAB 8388608ull
#define WSZ  1048576ull
// scratch sized as before (fp32 slabs); half buffers reuse regions loosely.
__device__ float g_scratch[9ull * SLAB + (unsigned long long)TOKENS * MLPH
                           + 4ull * WSZ + 2ull * (unsigned long long)CDIM * MLPH];

// ===========================================================================
// helpers
// ===========================================================================
__device__ __forceinline__ float4 blockReduce4(float4 v) {
    __shared__ float4 red[8];
    #pragma unroll
    for (int o = 16; o > 0; o >>= 1) {
        v.x += __shfl_xor_sync(0xffffffffu, v.x, o);
        v.y += __shfl_xor_sync(0xffffffffu, v.y, o);
        v.z += __shfl_xor_sync(0xffffffffu, v.z, o);
        v.w += __shfl_xor_sync(0xffffffffu, v.w, o);
    }
    int w = threadIdx.x >> 5;
    if ((threadIdx.x & 31) == 0) red[w] = v;
    __syncthreads();
    v = red[threadIdx.x & 7];
    #pragma unroll
    for (int o = 4; o > 0; o >>= 1) {
        v.x += __shfl_xor_sync(0xffffffffu, v.x, o);
        v.y += __shfl_xor_sync(0xffffffffu, v.y, o);
        v.z += __shfl_xor_sync(0xffffffffu, v.z, o);
        v.w += __shfl_xor_sync(0xffffffffu, v.w, o);
    }
    return v;
}

__device__ __forceinline__ unsigned f2h2(float x, float y) {
    __half2 h = __float22half2_rn(make_float2(x, y));
    return *reinterpret_cast<unsigned*>(&h);
}

__device__ __forceinline__ void mma_fp16(float* d, const unsigned* a,
                                         const unsigned* b) {
    asm volatile(
        "mma.sync.aligned.m16n8k16.row.col.f32.f16.f16.f32 "
        "{%0,%1,%2,%3}, {%4,%5,%6,%7}, {%8,%9}, {%0,%1,%2,%3};\n"
        : "+f"(d[0]), "+f"(d[1]), "+f"(d[2]), "+f"(d[3])
        : "r"(a[0]), "r"(a[1]), "r"(a[2]), "r"(a[3]),
          "r"(b[0]), "r"(b[1]));
}

// ===========================================================================
// LayerNorm kernels (emit fp16)
// ===========================================================================
__global__ __launch_bounds__(256) void ln_qkv_kernel(
    const float* __restrict__ x, const float* __restrict__ pe,
    const float* __restrict__ nqg, const float* __restrict__ nqb,
    const float* __restrict__ nkg, const float* __restrict__ nkb,
    const float* __restrict__ nvg, const float* __restrict__ nvb,
    __half* __restrict__ lnq, __half* __restrict__ lnk,
    __half* __restrict__ lnv)
{
    int t = blockIdx.x;
    int n = t & (NSEQ - 1);
    int tid = threadIdx.x;

    const float4* xr = (const float4*)(x + (size_t)t * CDIM);
    const float4* pr = (const float4*)(pe + (size_t)n * CDIM);
    float4 xv = xr[tid];
    float4 pv = pr[tid];
    float4 xp = make_float4(xv.x + pv.x, xv.y + pv.y, xv.z + pv.z, xv.w + pv.w);

    float4 s;
    s.x = xv.x + xv.y + xv.z + xv.w;
    s.y = xv.x * xv.x + xv.y * xv.y + xv.z * xv.z + xv.w * xv.w;
    s.z = xp.x + xp.y + xp.z + xp.w;
    s.w = xp.x * xp.x + xp.y * xp.y + xp.z * xp.z + xp.w * xp.w;
    s = blockReduce4(s);

    const float inv = 1.0f / (float)CDIM;
    float m1 = s.x * inv, v1 = s.y * inv - m1 * m1;
    float r1 = rsqrtf(v1 + LN_EPS);
    float m2 = s.z * inv, v2 = s.w * inv - m2 * m2;
    float r2 = rsqrtf(v2 + LN_EPS);

    float4 g, b;
    size_t base = (size_t)t * CDIM;

    g = ((const float4*)nqg)[tid]; b = ((const float4*)nqb)[tid];
    {
        float o0 = (xv.x - m1) * r1 * g.x + b.x;
        float o1 = (xv.y - m1) * r1 * g.y + b.y;
        float o2 = (xv.z - m1) * r1 * g.z + b.z;
        float o3 = (xv.w - m1) * r1 * g.w + b.w;
        ((uint2*)(lnq + base))[tid] = make_uint2(f2h2(o0, o1), f2h2(o2, o3));
    }

    float4 nrm;
    nrm.x = (xp.x - m2) * r2; nrm.y = (xp.y - m2) * r2;
    nrm.z = (xp.z - m2) * r2; nrm.w = (xp.w - m2) * r2;

    g = ((const float4*)nkg)[tid]; b = ((const float4*)nkb)[tid];
    {
        float o0 = nrm.x * g.x + b.x, o1 = nrm.y * g.y + b.y;
        float o2 = nrm.z * g.z + b.z, o3 = nrm.w * g.w + b.w;
        ((uint2*)(lnk + base))[tid] = make_uint2(f2h2(o0, o1), f2h2(o2, o3));
    }

    g = ((const float4*)nvg)[tid]; b = ((const float4*)nvb)[tid];
    {
        float o0 = nrm.x * g.x + b.x, o1 = nrm.y * g.y + b.y;
        float o2 = nrm.z * g.z + b.z, o3 = nrm.w * g.w + b.w;
        ((uint2*)(lnv + base))[tid] = make_uint2(f2h2(o0, o1), f2h2(o2, o3));
    }
}

__global__ __launch_bounds__(256) void ln_kernel(
    const float* __restrict__ in, const float* __restrict__ gg,
    const float* __restrict__ bb, __half* __restrict__ out)
{
    int t = blockIdx.x;
    int tid = threadIdx.x;
    const float4* xr = (const float4*)(in + (size_t)t * CDIM);
    float4 xv = xr[tid];
    float4 s;
    s.x = xv.x + xv.y + xv.z + xv.w;
    s.y = xv.x * xv.x + xv.y * xv.y + xv.z * xv.z + xv.w * xv.w;
    s.z = 0.f; s.w = 0.f;
    s = blockReduce4(s);
    const float inv = 1.0f / (float)CDIM;
    float m = s.x * inv, v = s.y * inv - m * m;
    float r = rsqrtf(v + LN_EPS);
    float4 g = ((const float4*)gg)[tid];
    float4 b = ((const float4*)bb)[tid];
    float o0 = (xv.x - m) * r * g.x + b.x;
    float o1 = (xv.y - m) * r * g.y + b.y;
    float o2 = (xv.z - m) * r * g.z + b.z;
    float o3 = (xv.w - m) * r * g.w + b.w;
    ((uint2*)(out + (size_t)t * CDIM))[tid] = make_uint2(f2h2(o0, o1), f2h2(o2, o3));
}

// ===========================================================================
// weight transpose + fp16 convert: W[R][C] (f32) -> Wt[C][R] (f16)
// ===========================================================================
__global__ __launch_bounds__(256) void transpose_kernel(
    const float* __restrict__ W, __half* __restrict__ Wt, int R, int C)
{
    __shared__ float t[32][33];
    int bx = blockIdx.x * 32;
    int by = blockIdx.y * 32;
    int tx = threadIdx.x & 31, ty4 = (threadIdx.x >> 5) * 4;
    #pragma unroll
    for (int j = 0; j < 4; j++)
        t[ty4 + j][tx] = W[(size_t)(by + ty4 + j) * C + bx + tx];
    __syncthreads();
    #pragma unroll
    for (int j = 0; j < 4; j++)
        Wt[(size_t)(bx + ty4 + j) * R + by + tx] = __float2half(t[tx][ty4 + j]);
}

// ===========================================================================
// fp16 GEMM (all-half operands): Y = X[M,K] @ WT[N,K]^T + bias.
// 128x128 tile, BK=32, double-buffered, 8 warps (2x4), 64x32/warp, m16n8k16.
// Staging = pure uint4 copy (no cvt). As/Bs [row][k] halves, stride 40.
// EPI: 0 bias->half ; 1 bias+LeakyReLU->half ; 2 bias+residual->float ;
//      3 bias, transposed->half (Y is [N][M]).
// ===========================================================================
#define GASTR 40

template <int EPI>
__global__ __launch_bounds__(256) void gemm_fp16(
    const __half* __restrict__ X, const __half* __restrict__ WT,
    const float* __restrict__ bias, const float* __restrict__ Res,
    void* __restrict__ Yv, int M, int N, int K)
{
    __shared__ __half As[2][128][GASTR];
    __shared__ __half Bs[2][128][GASTR];

    int tid = threadIdx.x;
    int bm = blockIdx.y * 128;
    int bn = blockIdx.x * 128;

    int warp = tid >> 5, lane = tid & 31;
    int wm = (warp & 1) * 64;
    int wn = (warp >> 1) * 32;
    int tg = lane & 3, gid = lane >> 2;

    int lr = tid >> 1;            // staging row 0..127
    int lc = (tid & 1) * 16;      // staging k offset (halves) 0 or 16

    float acc[4][4][4];
    #pragma unroll
    for (int i = 0; i < 4; i++)
        #pragma unroll
        for (int j = 0; j < 4; j++)
            #pragma unroll
            for (int r = 0; r < 4; r++) acc[i][j][r] = 0.f;

    const __half* Aptr = X + (size_t)(bm + lr) * K + lc;
    const __half* Bptr = WT + (size_t)(bn + lr) * K + lc;

    uint4 pa0 = *(const uint4*)(Aptr);
    uint4 pa1 = *(const uint4*)(Aptr + 8);
    uint4 pb0 = *(const uint4*)(Bptr);
    uint4 pb1 = *(const uint4*)(Bptr + 8);

    *(uint4*)&As[0][lr][lc]     = pa0;
    *(uint4*)&As[0][lr][lc + 8] = pa1;
    *(uint4*)&Bs[0][lr][lc]     = pb0;
    *(uint4*)&Bs[0][lr][lc + 8] = pb1;
    __syncthreads();

    for (int k0 = 0; k0 < K; k0 += 32) {
        int cur = (k0 >> 5) & 1;
        int nxt = cur ^ 1;
        bool has_next = (k0 + 32 < K);

        if (has_next) {
            pa0 = *(const uint4*)(Aptr + k0 + 32);
            pa1 = *(const uint4*)(Aptr + k0 + 40);
            pb0 = *(const uint4*)(Bptr + k0 + 32);
            pb1 = *(const uint4*)(Bptr + k0 + 40);
        }

        #pragma unroll
        for (int kk = 0; kk < 2; kk++) {
            int kb = kk * 16;
            unsigned af[4][4];
            #pragma unroll
            for (int mi = 0; mi < 4; mi++) {
                int r = wm + mi * 16 + gid;
                af[mi][0] = *(const unsigned*)&As[cur][r][kb + 2 * tg];
                af[mi][1] = *(const unsigned*)&As[cur][r + 8][kb + 2 * tg];
                af[mi][2] = *(const unsigned*)&As[cur][r][kb + 2 * tg + 8];
                af[mi][3] = *(const unsigned*)&As[cur][r + 8][kb + 2 * tg + 8];
            }
            unsigned bf[4][2];
            #pragma unroll
            for (int ni = 0; ni < 4; ni++) {
                int c = wn + ni * 8 + gid;
                bf[ni][0] = *(const unsigned*)&Bs[cur][c][kb + 2 * tg];
                bf[ni][1] = *(const unsigned*)&Bs[cur][c][kb + 2 * tg + 8];
            }
            #pragma unroll
            for (int mi = 0; mi < 4; mi++)
                #pragma unroll
                for (int ni = 0; ni < 4; ni++)
                    mma_fp16(acc[mi][ni], af[mi], bf[ni]);
        }

        if (has_next) {
            *(uint4*)&As[nxt][lr][lc]     = pa0;
            *(uint4*)&As[nxt][lr][lc + 8] = pa1;
            *(uint4*)&Bs[nxt][lr][lc]     = pb0;
            *(uint4*)&Bs[nxt][lr][lc + 8] = pb1;
        }
        __syncthreads();
    }

    // ---- epilogue (C frag: rows gid,gid+8; cols 2tg,2tg+1 per n-frag) ----
    if (EPI == 3) {
        __half* Y = (__half*)Yv;
        #pragma unroll
        for (int mi = 0; mi < 4; mi++) {
            int r0 = bm + wm + mi * 16 + gid;
            int r1 = r0 + 8;
            #pragma unroll
            for (int ni = 0; ni < 4; ni++) {
                int col = bn + wn + ni * 8 + 2 * tg;
                float bs0 = bias[col], bs1 = bias[col + 1];
                Y[(size_t)col * M + r0]       = __float2half(acc[mi][ni][0] + bs0);
                Y[(size_t)(col + 1) * M + r0] = __float2half(acc[mi][ni][1] + bs1);
                Y[(size_t)col * M + r1]       = __float2half(acc[mi][ni][2] + bs0);
                Y[(size_t)(col + 1) * M + r1] = __float2half(acc[mi][ni][3] + bs1);
            }
        }
        return;
    }

    if (EPI == 2) {
        float* Y = (float*)Yv;
        #pragma unroll
        for (int mi = 0; mi < 4; mi++) {
            int r0 = bm + wm + mi * 16 + gid;
            int r1 = r0 + 8;
            #pragma unroll
            for (int ni = 0; ni < 4; ni++) {
                int col = bn + wn + ni * 8 + 2 * tg;
                float2 bs = *(const float2*)(bias + col);
                float2 q0 = *(const float2*)(Res + (size_t)r0 * N + col);
                float2 q1 = *(const float2*)(Res + (size_t)r1 * N + col);
                float2 v0, v1;
                v0.x = acc[mi][ni][0] + bs.x + q0.x;
                v0.y = acc[mi][ni][1] + bs.y + q0.y;
                v1.x = acc[mi][ni][2] + bs.x + q1.x;
                v1.y = acc[mi][ni][3] + bs.y + q1.y;
                *(float2*)(Y + (size_t)r0 * N + col) = v0;
                *(float2*)(Y + (size_t)r1 * N + col) = v1;
            }
        }
        return;
    }

    // EPI 0 / 1 -> half output
    {
        __half* Y = (__half*)Yv;
        #pragma unroll
        for (int mi = 0; mi < 4; mi++) {
            int r0 = bm + wm + mi * 16 + gid;
            int r1 = r0 + 8;
            #pragma unroll
            for (int ni = 0; ni < 4; ni++) {
                int col = bn + wn + ni * 8 + 2 * tg;
                float2 bs = *(const float2*)(bias + col);
                float a0 = acc[mi][ni][0] + bs.x;
                float a1 = acc[mi][ni][1] + bs.y;
                float a2 = acc[mi][ni][2] + bs.x;
                float a3 = acc[mi][ni][3] + bs.y;
                if (EPI == 1) {
                    a0 = a0 >= 0.f ? a0 : 0.1f * a0;
                    a1 = a1 >= 0.f ? a1 : 0.1f * a1;
                    a2 = a2 >= 0.f ? a2 : 0.1f * a2;
                    a3 = a3 >= 0.f ? a3 : 0.1f * a3;
                }
                *(unsigned*)&Y[(size_t)r0 * N + col] = f2h2(a0, a1);
                *(unsigned*)&Y[(size_t)r1 * N + col] = f2h2(a2, a3);
            }
        }
    }
}

// ===========================================================================
// Flash-attention v5: all-fp16 operands, fp16 m16n8k16, fp32 softmax/accum.
// Q,K half [tok][CDIM]; V half [CDIM][tok]; O half [tok][CDIM].
// Scale applied post-mma in fp32 (staging is a pure copy).
// smem (halves): Qs[128][72], Ks[128][72], Vs[64][136], Ps[128][136].
// ===========================================================================
#define QS_STR 72
#define VS_STR 136
#define PS_STR 136
#define A4_QH (128 * QS_STR)
#define A4_VH (64 * VS_STR)
#define A4_PH (128 * PS_STR)
#define ATT4_SMEM_BYTES ((2 * A4_QH + A4_VH + A4_PH) * 2)

__global__ __launch_bounds__(256) void attn5_kernel(
    const __half* __restrict__ Q, const __half* __restrict__ K,
    const __half* __restrict__ VT, __half* __restrict__ O)
{
    extern __shared__ __half hsm[];
    __half* Qs = hsm;
    __half* Ks = hsm + A4_QH;
    __half* Vs = hsm + 2 * A4_QH;
    __half* Ps = hsm + 2 * A4_QH + A4_VH;

    int qt = blockIdx.x;
    int bh = blockIdx.y;
    int b = bh >> 4, h = bh & 15;

    int tid = threadIdx.x;
    int warp = tid >> 5, lane = tid & 31;
    int gid = lane >> 2, tg = lane & 3;
    int wq = warp * 16;

    const size_t tokbase = (size_t)b * NSEQ;
    const __half* qb = Q + (tokbase + (size_t)qt * 128) * CDIM + h * DHEAD;
    const __half* kb = K + tokbase * CDIM + h * DHEAD;
    const __half* vtb = VT + (size_t)(h * DHEAD) * TOKENS + tokbase;

    const float scale = 0.125f;

    // stage Q [q][d] (pure copy; 128 rows x 8 uint4)
    for (int i = tid; i < 128 * 8; i += 256) {
        int q = i >> 3, c = i & 7;
        *(uint4*)&Qs[q * QS_STR + c * 8] =
            *(const uint4*)(qb + (size_t)q * CDIM + c * 8);
    }

    float m0 = -INFINITY, m1 = -INFINITY, l0 = 0.f, l1 = 0.f;
    float o[8][4];
    #pragma unroll
    for (int ni = 0; ni < 8; ni++)
        #pragma unroll
        for (int r = 0; r < 4; r++) o[ni][r] = 0.f;

    for (int kt = 0; kt < NSEQ / 128; kt++) {
        __syncthreads();
        // stage K [k][d]
        for (int i = tid; i < 128 * 8; i += 256) {
            int k = i >> 3, c = i & 7;
            *(uint4*)&Ks[k * QS_STR + c * 8] =
                *(const uint4*)(kb + (size_t)(kt * 128 + k) * CDIM + c * 8);
        }
        // stage V [d][k]
        for (int i = tid; i < 64 * 16; i += 256) {
            int d = i >> 4, c = i & 15;
            *(uint4*)&Vs[d * VS_STR + c * 8] =
                *(const uint4*)(vtb + (size_t)d * TOKENS
                                + (size_t)kt * 128 + c * 8);
        }
        __syncthreads();

        // ---- S = Q·K^T ----
        float s[16][4];
        #pragma unroll
        for (int ni = 0; ni < 16; ni++)
            #pragma unroll
            for (int r = 0; r < 4; r++) s[ni][r] = 0.f;

        #pragma unroll
        for (int d0 = 0; d0 < 64; d0 += 16) {
            unsigned af[4];
            af[0] = *(const unsigned*)&Qs[(wq + gid) * QS_STR + d0 + 2 * tg];
            af[1] = *(const unsigned*)&Qs[(wq + gid + 8) * QS_STR + d0 + 2 * tg];
            af[2] = *(const unsigned*)&Qs[(wq + gid) * QS_STR + d0 + 2 * tg + 8];
            af[3] = *(const unsigned*)&Qs[(wq + gid + 8) * QS_STR + d0 + 2 * tg + 8];
            #pragma unroll
            for (int ni = 0; ni < 16; ni++) {
                unsigned bf[2];
                bf[0] = *(const unsigned*)&Ks[(ni * 8 + gid) * QS_STR + d0 + 2 * tg];
                bf[1] = *(const unsigned*)&Ks[(ni * 8 + gid) * QS_STR + d0 + 2 * tg + 8];
                mma_fp16(s[ni], af, bf);
            }
        }
        // apply softmax scale post-mma (fp32)
        #pragma unroll
        for (int ni = 0; ni < 16; ni++) {
            s[ni][0] *= scale; s[ni][1] *= scale;
            s[ni][2] *= scale; s[ni][3] *= scale;
        }

        // ---- online softmax ----
        float rm0 = -INFINITY, rm1 = -INFINITY;
        #pragma unroll
        for (int ni = 0; ni < 16; ni++) {
            rm0 = fmaxf(rm0, fmaxf(s[ni][0], s[ni][1]));
            rm1 = fmaxf(rm1, fmaxf(s[ni][2], s[ni][3]));
        }
        rm0 = fmaxf(rm0, __shfl_xor_sync(0xffffffffu, rm0, 1));
        rm0 = fmaxf(rm0, __shfl_xor_sync(0xffffffffu, rm0, 2));
        rm1 = fmaxf(rm1, __shfl_xor_sync(0xffffffffu, rm1, 1));
        rm1 = fmaxf(rm1, __shfl_xor_sync(0xffffffffu, rm1, 2));

        float mn0 = fmaxf(m0, rm0);
        float mn1 = fmaxf(m1, rm1);
        float al0 = __expf(m0 - mn0);
        float al1 = __expf(m1 - mn1);
        m0 = mn0; m1 = mn1;

        float rs0 = 0.f, rs1 = 0.f;
        #pragma unroll
        for (int ni = 0; ni < 16; ni++) {
            s[ni][0] = __expf(s[ni][0] - m0);
            s[ni][1] = __expf(s[ni][1] - m0);
            s[ni][2] = __expf(s[ni][2] - m1);
            s[ni][3] = __expf(s[ni][3] - m1);
            rs0 += s[ni][0] + s[ni][1];
            rs1 += s[ni][2] + s[ni][3];
        }
        rs0 += __shfl_xor_sync(0xffffffffu, rs0, 1);
        rs0 += __shfl_xor_sync(0xffffffffu, rs0, 2);
        rs1 += __shfl_xor_sync(0xffffffffu, rs1, 1);
        rs1 += __shfl_xor_sync(0xffffffffu, rs1, 2);
        l0 = l0 * al0 + rs0;
        l1 = l1 * al1 + rs1;

        #pragma unroll
        for (int ni = 0; ni < 8; ni++) {
            o[ni][0] *= al0; o[ni][1] *= al0;
            o[ni][2] *= al1; o[ni][3] *= al1;
        }

        // ---- store P (half2, own rows only) ----
        #pragma unroll
        for (int ni = 0; ni < 16; ni++) {
            *(unsigned*)&Ps[(wq + gid) * PS_STR + ni * 8 + 2 * tg] =
                f2h2(s[ni][0], s[ni][1]);
            *(unsigned*)&Ps[(wq + gid + 8) * PS_STR + ni * 8 + 2 * tg] =
                f2h2(s[ni][2], s[ni][3]);
        }
        __syncwarp();

        // ---- O += P·V ----
        #pragma unroll
        for (int k0 = 0; k0 < 128; k0 += 16) {
            unsigned af[4];
            af[0] = *(const unsigned*)&Ps[(wq + gid) * PS_STR + k0 + 2 * tg];
            af[1] = *(const unsigned*)&Ps[(wq + gid + 8) * PS_STR + k0 + 2 * tg];
            af[2] = *(const unsigned*)&Ps[(wq + gid) * PS_STR + k0 + 2 * tg + 8];
            af[3] = *(const unsigned*)&Ps[(wq + gid + 8) * PS_STR + k0 + 2 * tg + 8];
            #pragma unroll
            for (int ni = 0; ni < 8; ni++) {
                unsigned bf[2];
                bf[0] = *(const unsigned*)&Vs[(ni * 8 + gid) * VS_STR + k0 + 2 * tg];
                bf[1] = *(const unsigned*)&Vs[(ni * 8 + gid) * VS_STR + k0 + 2 * tg + 8];
                mma_fp16(o[ni], af, bf);
            }
        }
    }

    // ---- normalize + write half output ----
    float inv0 = 1.0f / l0;
    float inv1 = 1.0f / l1;
    size_t row0 = tokbase + (size_t)qt * 128 + wq + gid;
    size_t row1 = row0 + 8;
    #pragma unroll
    for (int ni = 0; ni < 8; ni++) {
        int col = h * DHEAD + ni * 8 + 2 * tg;
        *(unsigned*)&O[row0 * CDIM + col] = f2h2(o[ni][0] * inv0, o[ni][1] * inv0);
        *(unsigned*)&O[row1 * CDIM + col] = f2h2(o[ni][2] * inv1, o[ni][3] * inv1);
    }
}

// ===========================================================================
// Launch
// ===========================================================================
extern "C" void kernel_launch(void* const* d_in, const int* in_sizes, int n_in,
                              void* d_out, int out_size)
{
    bool dict_order = (in_sizes[8] == CDIM);

    const float* x   = (const float*)d_in[0];
    const float* pe  = (const float*)d_in[1];
    const float* nqg = (const float*)d_in[2];
    const float* nqb = (const float*)d_in[3];
    const float* nkg = (const float*)d_in[4];
    const float* nkb = (const float*)d_in[5];
    const float* nvg = (const float*)d_in[6];
    const float* nvb = (const float*)d_in[7];

    const float *ng, *nb, *wq, *bq, *wk, *bk, *wv, *bv, *wp, *bp,
                *w1, *b1, *w2, *b2;
    if (dict_order) {
        ng = (const float*)d_in[8];  nb = (const float*)d_in[9];
        wq = (const float*)d_in[10]; bq = (const float*)d_in[11];
        wk = (const float*)d_in[12]; bk = (const float*)d_in[13];
        wv = (const float*)d_in[14]; bv = (const float*)d_in[15];
        wp = (const float*)d_in[16]; bp = (const float*)d_in[17];
        w1 = (const float*)d_in[18]; b1 = (const float*)d_in[19];
        w2 = (const float*)d_in[20]; b2 = (const float*)d_in[21];
    } else {
        wq = (const float*)d_in[8];  bq = (const float*)d_in[9];
        wk = (const float*)d_in[10]; bk = (const float*)d_in[11];
        wv = (const float*)d_in[12]; bv = (const float*)d_in[13];
        wp = (const float*)d_in[14]; bp = (const float*)d_in[15];
        ng = (const float*)d_in[16]; nb = (const float*)d_in[17];
        w1 = (const float*)d_in[18]; b1 = (const float*)d_in[19];
        w2 = (const float*)d_in[20]; b2 = (const float*)d_in[21];
    }
    float* out = (float*)d_out;

    float* sc = nullptr;
    cudaGetSymbolAddress((void**)&sc, g_scratch);
    // half buffers (each fits easily in its fp32-sized region)
    __half* lnq = (__half*)(sc + 0 * SLAB);
    __half* lnk = (__half*)(sc + 1 * SLAB);
    __half* lnv = (__half*)(sc + 2 * SLAB);
    __half* q   = (__half*)(sc + 3 * SLAB);   // [TOKENS][CDIM]
    __half* k   = (__half*)(sc + 4 * SLAB);   // [TOKENS][CDIM]
    __half* vT  = (__half*)(sc + 5 * SLAB);   // [CDIM][TOKENS]
    __half* ao  = (__half*)(sc + 6 * SLAB);   // [TOKENS][CDIM]
    float*  hbuf= sc + 7 * SLAB;              // fp32 (residual h)
    __half* lnh = (__half*)(sc + 8 * SLAB);
    __half* m1  = (__half*)(sc + 9 * SLAB);   // [TOKENS][MLPH]
    float*  wbase = sc + 9 * SLAB + (size_t)TOKENS * MLPH;
    __half* wqT = (__half*)(wbase);           // [C][C]
    __half* wkT = (__half*)(wbase + WSZ);
    __half* wvT = (__half*)(wbase + 2 * WSZ);
    __half* wpT = (__half*)(wbase + 3 * WSZ);
    __half* w1T = (__half*)(wbase + 4 * WSZ);            // [MLPH][C]
    __half* w2T = (__half*)(wbase + 4 * WSZ + (size_t)CDIM * MLPH); // [C][MLPH] (half fits)

    cudaFuncSetAttribute(attn5_kernel,
                         cudaFuncAttributeMaxDynamicSharedMemorySize,
                         ATT4_SMEM_BYTES);

    // order keeps first gemm at launch index 5 for ncu -s 5
    transpose_kernel<<<dim3(CDIM / 32, CDIM / 32), 256>>>(wq, wqT, CDIM, CDIM);
    transpose_kernel<<<dim3(CDIM / 32, CDIM / 32), 256>>>(wk, wkT, CDIM, CDIM);
    transpose_kernel<<<dim3(CDIM / 32, CDIM / 32), 256>>>(wv, wvT, CDIM, CDIM);

    ln_qkv_kernel<<<TOKENS, 256>>>(x, pe, nqg, nqb, nkg, nkb, nvg, nvb,
                                   lnq, lnk, lnv);

    transpose_kernel<<<dim3(CDIM / 32, CDIM / 32), 256>>>(wp, wpT, CDIM, CDIM);

    // QKV projections
    dim3 gC(CDIM / 128, TOKENS / 128);
    gemm_fp16<0><<<gC, 256>>>(lnq, wqT, bq, nullptr, q, TOKENS, CDIM, CDIM);
    gemm_fp16<0><<<gC, 256>>>(lnk, wkT, bk, nullptr, k, TOKENS, CDIM, CDIM);
    gemm_fp16<3><<<gC, 256>>>(lnv, wvT, bv, nullptr, vT, TOKENS, CDIM, CDIM);

    transpose_kernel<<<dim3(MLPH / 32, CDIM / 32), 256>>>(w1, w1T, CDIM, MLPH);
    transpose_kernel<<<dim3(CDIM / 32, MLPH / 32), 256>>>(w2, w2T, MLPH, CDIM);

    // Attention
    dim3 gA(NSEQ / 128, 4 * NHEADS);
    attn5_kernel<<<gA, 256, ATT4_SMEM_BYTES>>>(q, k, vT, ao);

    // Output projection + residual (fp32 out)
    gemm_fp16<2><<<gC, 256>>>(ao, wpT, bp, x, hbuf, TOKENS, CDIM, CDIM);

    // LN(h) -> half
    ln_kernel<<<TOKENS, 256>>>(hbuf, ng, nb, lnh);

    // MLP1 + LeakyReLU -> half
    dim3 gH(MLPH / 128, TOKENS / 128);
    gemm_fp16<1><<<gH, 256>>>(lnh, w1T, b1, nullptr, m1, TOKENS, MLPH, CDIM);

    // MLP2 + residual -> fp32 out
    gemm_fp16<2><<<gC, 256>>>(m1, w2T, b2, hbuf, out, TOKENS, CDIM, MLPH);
}

// round 17
// speedup vs baseline: 1.7871x; 1.0747x over previous
#include <cuda_runtime.h>
#include <cuda_fp16.h>
#include <stdint.h>
#include <math.h>

#define TOKENS 8192
#define NSEQ   2048
#define CDIM   1024
#define MLPH   4096
#define NHEADS 16
#define DHEAD  64
#define LN_EPS 1e-5f

#define SLAB 8388608ull
#define WSZ  1048576ull
__device__ float g_scratch[9ull * SLAB + (unsigned long long)TOKENS * MLPH
                           + 4ull * WSZ + 2ull * (unsigned long long)CDIM * MLPH];

// ===========================================================================
// helpers
// ===========================================================================
__device__ __forceinline__ float4 blockReduce4(float4 v) {
    __shared__ float4 red[8];
    #pragma unroll
    for (int o = 16; o > 0; o >>= 1) {
        v.x += __shfl_xor_sync(0xffffffffu, v.x, o);
        v.y += __shfl_xor_sync(0xffffffffu, v.y, o);
        v.z += __shfl_xor_sync(0xffffffffu, v.z, o);
        v.w += __shfl_xor_sync(0xffffffffu, v.w, o);
    }
    int w = threadIdx.x >> 5;
    if ((threadIdx.x & 31) == 0) red[w] = v;
    __syncthreads();
    v = red[threadIdx.x & 7];
    #pragma unroll
    for (int o = 4; o > 0; o >>= 1) {
        v.x += __shfl_xor_sync(0xffffffffu, v.x, o);
        v.y += __shfl_xor_sync(0xffffffffu, v.y, o);
        v.z += __shfl_xor_sync(0xffffffffu, v.z, o);
        v.w += __shfl_xor_sync(0xffffffffu, v.w, o);
    }
    return v;
}

__device__ __forceinline__ unsigned f2h2(float x, float y) {
    __half2 h = __float22half2_rn(make_float2(x, y));
    return *reinterpret_cast<unsigned*>(&h);
}

__device__ __forceinline__ void mma_fp16(float* d, const unsigned* a,
                                         const unsigned* b) {
    asm volatile(
        "mma.sync.aligned.m16n8k16.row.col.f32.f16.f16.f32 "
        "{%0,%1,%2,%3}, {%4,%5,%6,%7}, {%8,%9}, {%0,%1,%2,%3};\n"
        : "+f"(d[0]), "+f"(d[1]), "+f"(d[2]), "+f"(d[3])
        : "r"(a[0]), "r"(a[1]), "r"(a[2]), "r"(a[3]),
          "r"(b[0]), "r"(b[1]));
}

__device__ __forceinline__ void cp_async16(void* smem_dst, const void* gsrc) {
    unsigned saddr = (unsigned)__cvta_generic_to_shared(smem_dst);
    asm volatile("cp.async.cg.shared.global [%0], [%1], 16;\n"
                 :: "r"(saddr), "l"(gsrc));
}
#define CP_COMMIT() asm volatile("cp.async.commit_group;\n" ::: "memory")
#define CP_WAIT0()  asm volatile("cp.async.wait_group 0;\n" ::: "memory")

// ===========================================================================
// LayerNorm kernels (emit fp16)
// ===========================================================================
__global__ __launch_bounds__(256) void ln_qkv_kernel(
    const float* __restrict__ x, const float* __restrict__ pe,
    const float* __restrict__ nqg, const float* __restrict__ nqb,
    const float* __restrict__ nkg, const float* __restrict__ nkb,
    const float* __restrict__ nvg, const float* __restrict__ nvb,
    __half* __restrict__ lnq, __half* __restrict__ lnk,
    __half* __restrict__ lnv)
{
    int t = blockIdx.x;
    int n = t & (NSEQ - 1);
    int tid = threadIdx.x;

    const float4* xr = (const float4*)(x + (size_t)t * CDIM);
    const float4* pr = (const float4*)(pe + (size_t)n * CDIM);
    float4 xv = xr[tid];
    float4 pv = pr[tid];
    float4 xp = make_float4(xv.x + pv.x, xv.y + pv.y, xv.z + pv.z, xv.w + pv.w);

    float4 s;
    s.x = xv.x + xv.y + xv.z + xv.w;
    s.y = xv.x * xv.x + xv.y * xv.y + xv.z * xv.z + xv.w * xv.w;
    s.z = xp.x + xp.y + xp.z + xp.w;
    s.w = xp.x * xp.x + xp.y * xp.y + xp.z * xp.z + xp.w * xp.w;
    s = blockReduce4(s);

    const float inv = 1.0f / (float)CDIM;
    float m1 = s.x * inv, v1 = s.y * inv - m1 * m1;
    float r1 = rsqrtf(v1 + LN_EPS);
    float m2 = s.z * inv, v2 = s.w * inv - m2 * m2;
    float r2 = rsqrtf(v2 + LN_EPS);

    float4 g, b;
    size_t base = (size_t)t * CDIM;

    g = ((const float4*)nqg)[tid]; b = ((const float4*)nqb)[tid];
    {
        float o0 = (xv.x - m1) * r1 * g.x + b.x;
        float o1 = (xv.y - m1) * r1 * g.y + b.y;
        float o2 = (xv.z - m1) * r1 * g.z + b.z;
        float o3 = (xv.w - m1) * r1 * g.w + b.w;
        ((uint2*)(lnq + base))[tid] = make_uint2(f2h2(o0, o1), f2h2(o2, o3));
    }

    float4 nrm;
    nrm.x = (xp.x - m2) * r2; nrm.y = (xp.y - m2) * r2;
    nrm.z = (xp.z - m2) * r2; nrm.w = (xp.w - m2) * r2;

    g = ((const float4*)nkg)[tid]; b = ((const float4*)nkb)[tid];
    {
        float o0 = nrm.x * g.x + b.x, o1 = nrm.y * g.y + b.y;
        float o2 = nrm.z * g.z + b.z, o3 = nrm.w * g.w + b.w;
        ((uint2*)(lnk + base))[tid] = make_uint2(f2h2(o0, o1), f2h2(o2, o3));
    }

    g = ((const float4*)nvg)[tid]; b = ((const float4*)nvb)[tid];
    {
        float o0 = nrm.x * g.x + b.x, o1 = nrm.y * g.y + b.y;
        float o2 = nrm.z * g.z + b.z, o3 = nrm.w * g.w + b.w;
        ((uint2*)(lnv + base))[tid] = make_uint2(f2h2(o0, o1), f2h2(o2, o3));
    }
}

__global__ __launch_bounds__(256) void ln_kernel(
    const float* __restrict__ in, const float* __restrict__ gg,
    const float* __restrict__ bb, __half* __restrict__ out)
{
    int t = blockIdx.x;
    int tid = threadIdx.x;
    const float4* xr = (const float4*)(in + (size_t)t * CDIM);
    float4 xv = xr[tid];
    float4 s;
    s.x = xv.x + xv.y + xv.z + xv.w;
    s.y = xv.x * xv.x + xv.y * xv.y + xv.z * xv.z + xv.w * xv.w;
    s.z = 0.f; s.w = 0.f;
    s = blockReduce4(s);
    const float inv = 1.0f / (float)CDIM;
    float m = s.x * inv, v = s.y * inv - m * m;
    float r = rsqrtf(v + LN_EPS);
    float4 g = ((const float4*)gg)[tid];
    float4 b = ((const float4*)bb)[tid];
    float o0 = (xv.x - m) * r * g.x + b.x;
    float o1 = (xv.y - m) * r * g.y + b.y;
    float o2 = (xv.z - m) * r * g.z + b.z;
    float o3 = (xv.w - m) * r * g.w + b.w;
    ((uint2*)(out + (size_t)t * CDIM))[tid] = make_uint2(f2h2(o0, o1), f2h2(o2, o3));
}

// ===========================================================================
// weight transpose + fp16 convert: W[R][C] (f32) -> Wt[C][R] (f16)
// ===========================================================================
__global__ __launch_bounds__(256) void transpose_kernel(
    const float* __restrict__ W, __half* __restrict__ Wt, int R, int C)
{
    __shared__ float t[32][33];
    int bx = blockIdx.x * 32;
    int by = blockIdx.y * 32;
    int tx = threadIdx.x & 31, ty4 = (threadIdx.x >> 5) * 4;
    #pragma unroll
    for (int j = 0; j < 4; j++)
        t[ty4 + j][tx] = W[(size_t)(by + ty4 + j) * C + bx + tx];
    __syncthreads();
    #pragma unroll
    for (int j = 0; j < 4; j++)
        Wt[(size_t)(bx + ty4 + j) * R + by + tx] = __float2half(t[tx][ty4 + j]);
}

// ===========================================================================
// fp16 GEMM with cp.async staging: Y = X[M,K] @ WT[N,K]^T + bias.
// 128x128 tile, BK=32, double-buffered, 8 warps (2x4), 64x32/warp, m16n8k16.
// cp.async global->smem (no staging registers -> natural occupancy 2 CTA/SM).
// EPI: 0 bias->half ; 1 bias+LeakyReLU->half ; 2 bias+residual->float ;
//      3 bias, transposed->half (Y is [N][M]).
// ===========================================================================
#define GASTR 40

template <int EPI>
__global__ __launch_bounds__(256) void gemm_fp16(
    const __half* __restrict__ X, const __half* __restrict__ WT,
    const float* __restrict__ bias, const float* __restrict__ Res,
    void* __restrict__ Yv, int M, int N, int K)
{
    __shared__ __half As[2][128][GASTR];
    __shared__ __half Bs[2][128][GASTR];

    int tid = threadIdx.x;
    int bm = blockIdx.y * 128;
    int bn = blockIdx.x * 128;

    int warp = tid >> 5, lane = tid & 31;
    int wm = (warp & 1) * 64;
    int wn = (warp >> 1) * 32;
    int tg = lane & 3, gid = lane >> 2;

    int lr = tid >> 1;            // staging row 0..127
    int lc = (tid & 1) * 16;      // staging k offset (halves) 0 or 16

    float acc[4][4][4];
    #pragma unroll
    for (int i = 0; i < 4; i++)
        #pragma unroll
        for (int j = 0; j < 4; j++)
            #pragma unroll
            for (int r = 0; r < 4; r++) acc[i][j][r] = 0.f;

    const __half* Aptr = X + (size_t)(bm + lr) * K + lc;
    const __half* Bptr = WT + (size_t)(bn + lr) * K + lc;

    // prologue: stage buffer 0 via cp.async
    cp_async16(&As[0][lr][lc],     Aptr);
    cp_async16(&As[0][lr][lc + 8], Aptr + 8);
    cp_async16(&Bs[0][lr][lc],     Bptr);
    cp_async16(&Bs[0][lr][lc + 8], Bptr + 8);
    CP_COMMIT();
    CP_WAIT0();
    __syncthreads();

    for (int k0 = 0; k0 < K; k0 += 32) {
        int cur = (k0 >> 5) & 1;
        int nxt = cur ^ 1;
        bool has_next = (k0 + 32 < K);

        if (has_next) {
            cp_async16(&As[nxt][lr][lc],     Aptr + k0 + 32);
            cp_async16(&As[nxt][lr][lc + 8], Aptr + k0 + 40);
            cp_async16(&Bs[nxt][lr][lc],     Bptr + k0 + 32);
            cp_async16(&Bs[nxt][lr][lc + 8], Bptr + k0 + 40);
            CP_COMMIT();
        }

        #pragma unroll
        for (int kk = 0; kk < 2; kk++) {
            int kb = kk * 16;
            unsigned af[4][4];
            #pragma unroll
            for (int mi = 0; mi < 4; mi++) {
                int r = wm + mi * 16 + gid;
                af[mi][0] = *(const unsigned*)&As[cur][r][kb + 2 * tg];
                af[mi][1] = *(const unsigned*)&As[cur][r + 8][kb + 2 * tg];
                af[mi][2] = *(const unsigned*)&As[cur][r][kb + 2 * tg + 8];
                af[mi][3] = *(const unsigned*)&As[cur][r + 8][kb + 2 * tg + 8];
            }
            unsigned bf[4][2];
            #pragma unroll
            for (int ni = 0; ni < 4; ni++) {
                int c = wn + ni * 8 + gid;
                bf[ni][0] = *(const unsigned*)&Bs[cur][c][kb + 2 * tg];
                bf[ni][1] = *(const unsigned*)&Bs[cur][c][kb + 2 * tg + 8];
            }
            #pragma unroll
            for (int mi = 0; mi < 4; mi++)
                #pragma unroll
                for (int ni = 0; ni < 4; ni++)
                    mma_fp16(acc[mi][ni], af[mi], bf[ni]);
        }

        if (has_next) CP_WAIT0();
        __syncthreads();
    }

    // ---- epilogue (C frag: rows gid,gid+8; cols 2tg,2tg+1 per n-frag) ----
    if (EPI == 3) {
        __half* Y = (__half*)Yv;
        #pragma unroll
        for (int mi = 0; mi < 4; mi++) {
            int r0 = bm + wm + mi * 16 + gid;
            int r1 = r0 + 8;
            #pragma unroll
            for (int ni = 0; ni < 4; ni++) {
                int col = bn + wn + ni * 8 + 2 * tg;
                float bs0 = bias[col], bs1 = bias[col + 1];
                Y[(size_t)col * M + r0]       = __float2half(acc[mi][ni][0] + bs0);
                Y[(size_t)(col + 1) * M + r0] = __float2half(acc[mi][ni][1] + bs1);
                Y[(size_t)col * M + r1]       = __float2half(acc[mi][ni][2] + bs0);
                Y[(size_t)(col + 1) * M + r1] = __float2half(acc[mi][ni][3] + bs1);
            }
        }
        return;
    }

    if (EPI == 2) {
        float* Y = (float*)Yv;
        #pragma unroll
        for (int mi = 0; mi < 4; mi++) {
            int r0 = bm + wm + mi * 16 + gid;
            int r1 = r0 + 8;
            #pragma unroll
            for (int ni = 0; ni < 4; ni++) {
                int col = bn + wn + ni * 8 + 2 * tg;
                float2 bs = *(const float2*)(bias + col);
                float2 q0 = *(const float2*)(Res + (size_t)r0 * N + col);
                float2 q1 = *(const float2*)(Res + (size_t)r1 * N + col);
                float2 v0, v1;
                v0.x = acc[mi][ni][0] + bs.x + q0.x;
                v0.y = acc[mi][ni][1] + bs.y + q0.y;
                v1.x = acc[mi][ni][2] + bs.x + q1.x;
                v1.y = acc[mi][ni][3] + bs.y + q1.y;
                *(float2*)(Y + (size_t)r0 * N + col) = v0;
                *(float2*)(Y + (size_t)r1 * N + col) = v1;
            }
        }
        return;
    }

    {
        __half* Y = (__half*)Yv;
        #pragma unroll
        for (int mi = 0; mi < 4; mi++) {
            int r0 = bm + wm + mi * 16 + gid;
            int r1 = r0 + 8;
            #pragma unroll
            for (int ni = 0; ni < 4; ni++) {
                int col = bn + wn + ni * 8 + 2 * tg;
                float2 bs = *(const float2*)(bias + col);
                float a0 = acc[mi][ni][0] + bs.x;
                float a1 = acc[mi][ni][1] + bs.y;
                float a2 = acc[mi][ni][2] + bs.x;
                float a3 = acc[mi][ni][3] + bs.y;
                if (EPI == 1) {
                    a0 = a0 >= 0.f ? a0 : 0.1f * a0;
                    a1 = a1 >= 0.f ? a1 : 0.1f * a1;
                    a2 = a2 >= 0.f ? a2 : 0.1f * a2;
                    a3 = a3 >= 0.f ? a3 : 0.1f * a3;
                }
                *(unsigned*)&Y[(size_t)r0 * N + col] = f2h2(a0, a1);
                *(unsigned*)&Y[(size_t)r1 * N + col] = f2h2(a2, a3);
            }
        }
    }
}

// ===========================================================================
// Flash-attention v5 (unchanged from round 16)
// ===========================================================================
#define QS_STR 72
#define VS_STR 136
#define PS_STR 136
#define A4_QH (128 * QS_STR)
#define A4_VH (64 * VS_STR)
#define A4_PH (128 * PS_STR)
#define ATT4_SMEM_BYTES ((2 * A4_QH + A4_VH + A4_PH) * 2)

__global__ __launch_bounds__(256) void attn5_kernel(
    const __half* __restrict__ Q, const __half* __restrict__ K,
    const __half* __restrict__ VT, __half* __restrict__ O)
{
    extern __shared__ __half hsm[];
    __half* Qs = hsm;
    __half* Ks = hsm + A4_QH;
    __half* Vs = hsm + 2 * A4_QH;
    __half* Ps = hsm + 2 * A4_QH + A4_VH;

    int qt = blockIdx.x;
    int bh = blockIdx.y;
    int b = bh >> 4, h = bh & 15;

    int tid = threadIdx.x;
    int warp = tid >> 5, lane = tid & 31;
    int gid = lane >> 2, tg = lane & 3;
    int wq = warp * 16;

    const size_t tokbase = (size_t)b * NSEQ;
    const __half* qb = Q + (tokbase + (size_t)qt * 128) * CDIM + h * DHEAD;
    const __half* kb = K + tokbase * CDIM + h * DHEAD;
    const __half* vtb = VT + (size_t)(h * DHEAD) * TOKENS + tokbase;

    const float scale = 0.125f;

    for (int i = tid; i < 128 * 8; i += 256) {
        int q = i >> 3, c = i & 7;
        *(uint4*)&Qs[q * QS_STR + c * 8] =
            *(const uint4*)(qb + (size_t)q * CDIM + c * 8);
    }

    float m0 = -INFINITY, m1 = -INFINITY, l0 = 0.f, l1 = 0.f;
    float o[8][4];
    #pragma unroll
    for (int ni = 0; ni < 8; ni++)
        #pragma unroll
        for (int r = 0; r < 4; r++) o[ni][r] = 0.f;

    for (int kt = 0; kt < NSEQ / 128; kt++) {
        __syncthreads();
        for (int i = tid; i < 128 * 8; i += 256) {
            int k = i >> 3, c = i & 7;
            *(uint4*)&Ks[k * QS_STR + c * 8] =
                *(const uint4*)(kb + (size_t)(kt * 128 + k) * CDIM + c * 8);
        }
        for (int i = tid; i < 64 * 16; i += 256) {
            int d = i >> 4, c = i & 15;
            *(uint4*)&Vs[d * VS_STR + c * 8] =
                *(const uint4*)(vtb + (size_t)d * TOKENS
                                + (size_t)kt * 128 + c * 8);
        }
        __syncthreads();

        float s[16][4];
        #pragma unroll
        for (int ni = 0; ni < 16; ni++)
            #pragma unroll
            for (int r = 0; r < 4; r++) s[ni][r] = 0.f;

        #pragma unroll
        for (int d0 = 0; d0 < 64; d0 += 16) {
            unsigned af[4];
            af[0] = *(const unsigned*)&Qs[(wq + gid) * QS_STR + d0 + 2 * tg];
            af[1] = *(const unsigned*)&Qs[(wq + gid + 8) * QS_STR + d0 + 2 * tg];
            af[2] = *(const unsigned*)&Qs[(wq + gid) * QS_STR + d0 + 2 * tg + 8];
            af[3] = *(const unsigned*)&Qs[(wq + gid + 8) * QS_STR + d0 + 2 * tg + 8];
            #pragma unroll
            for (int ni = 0; ni < 16; ni++) {
                unsigned bf[2];
                bf[0] = *(const unsigned*)&Ks[(ni * 8 + gid) * QS_STR + d0 + 2 * tg];
                bf[1] = *(const unsigned*)&Ks[(ni * 8 + gid) * QS_STR + d0 + 2 * tg + 8];
                mma_fp16(s[ni], af, bf);
            }
        }
        #pragma unroll
        for (int ni = 0; ni < 16; ni++) {
            s[ni][0] *= scale; s[ni][1] *= scale;
            s[ni][2] *= scale; s[ni][3] *= scale;
        }

        float rm0 = -INFINITY, rm1 = -INFINITY;
        #pragma unroll
        for (int ni = 0; ni < 16; ni++) {
            rm0 = fmaxf(rm0, fmaxf(s[ni][0], s[ni][1]));
            rm1 = fmaxf(rm1, fmaxf(s[ni][2], s[ni][3]));
        }
        rm0 = fmaxf(rm0, __shfl_xor_sync(0xffffffffu, rm0, 1));
        rm0 = fmaxf(rm0, __shfl_xor_sync(0xffffffffu, rm0, 2));
        rm1 = fmaxf(rm1, __shfl_xor_sync(0xffffffffu, rm1, 1));
        rm1 = fmaxf(rm1, __shfl_xor_sync(0xffffffffu, rm1, 2));

        float mn0 = fmaxf(m0, rm0);
        float mn1 = fmaxf(m1, rm1);
        float al0 = __expf(m0 - mn0);
        float al1 = __expf(m1 - mn1);
        m0 = mn0; m1 = mn1;

        float rs0 = 0.f, rs1 = 0.f;
        #pragma unroll
        for (int ni = 0; ni < 16; ni++) {
            s[ni][0] = __expf(s[ni][0] - m0);
            s[ni][1] = __expf(s[ni][1] - m0);
            s[ni][2] = __expf(s[ni][2] - m1);
            s[ni][3] = __expf(s[ni][3] - m1);
            rs0 += s[ni][0] + s[ni][1];
            rs1 += s[ni][2] + s[ni][3];
        }
        rs0 += __shfl_xor_sync(0xffffffffu, rs0, 1);
        rs0 += __shfl_xor_sync(0xffffffffu, rs0, 2);
        rs1 += __shfl_xor_sync(0xffffffffu, rs1, 1);
        rs1 += __shfl_xor_sync(0xffffffffu, rs1, 2);
        l0 = l0 * al0 + rs0;
        l1 = l1 * al1 + rs1;

        #pragma unroll
        for (int ni = 0; ni < 8; ni++) {
            o[ni][0] *= al0; o[ni][1] *= al0;
            o[ni][2] *= al1; o[ni][3] *= al1;
        }

        #pragma unroll
        for (int ni = 0; ni < 16; ni++) {
            *(unsigned*)&Ps[(wq + gid) * PS_STR + ni * 8 + 2 * tg] =
                f2h2(s[ni][0], s[ni][1]);
            *(unsigned*)&Ps[(wq + gid + 8) * PS_STR + ni * 8 + 2 * tg] =
                f2h2(s[ni][2], s[ni][3]);
        }
        __syncwarp();

        #pragma unroll
        for (int k0 = 0; k0 < 128; k0 += 16) {
            unsigned af[4];
            af[0] = *(const unsigned*)&Ps[(wq + gid) * PS_STR + k0 + 2 * tg];
            af[1] = *(const unsigned*)&Ps[(wq + gid + 8) * PS_STR + k0 + 2 * tg];
            af[2] = *(const unsigned*)&Ps[(wq + gid) * PS_STR + k0 + 2 * tg + 8];
            af[3] = *(const unsigned*)&Ps[(wq + gid + 8) * PS_STR + k0 + 2 * tg + 8];
            #pragma unroll
            for (int ni = 0; ni < 8; ni++) {
                unsigned bf[2];
                bf[0] = *(const unsigned*)&Vs[(ni * 8 + gid) * VS_STR + k0 + 2 * tg];
                bf[1] = *(const unsigned*)&Vs[(ni * 8 + gid) * VS_STR + k0 + 2 * tg + 8];
                mma_fp16(o[ni], af, bf);
            }
        }
    }

    float inv0 = 1.0f / l0;
    float inv1 = 1.0f / l1;
    size_t row0 = tokbase + (size_t)qt * 128 + wq + gid;
    size_t row1 = row0 + 8;
    #pragma unroll
    for (int ni = 0; ni < 8; ni++) {
        int col = h * DHEAD + ni * 8 + 2 * tg;
        *(unsigned*)&O[row0 * CDIM + col] = f2h2(o[ni][0] * inv0, o[ni][1] * inv0);
        *(unsigned*)&O[row1 * CDIM + col] = f2h2(o[ni][2] * inv1, o[ni][3] * inv1);
    }
}

// ===========================================================================
// Launch
// ===========================================================================
extern "C" void kernel_launch(void* const* d_in, const int* in_sizes, int n_in,
                              void* d_out, int out_size)
{
    bool dict_order = (in_sizes[8] == CDIM);

    const float* x   = (const float*)d_in[0];
    const float* pe  = (const float*)d_in[1];
    const float* nqg = (const float*)d_in[2];
    const float* nqb = (const float*)d_in[3];
    const float* nkg = (const float*)d_in[4];
    const float* nkb = (const float*)d_in[5];
    const float* nvg = (const float*)d_in[6];
    const float* nvb = (const float*)d_in[7];

    const float *ng, *nb, *wq, *bq, *wk, *bk, *wv, *bv, *wp, *bp,
                *w1, *b1, *w2, *b2;
    if (dict_order) {
        ng = (const float*)d_in[8];  nb = (const float*)d_in[9];
        wq = (const float*)d_in[10]; bq = (const float*)d_in[11];
        wk = (const float*)d_in[12]; bk = (const float*)d_in[13];
        wv = (const float*)d_in[14]; bv = (const float*)d_in[15];
        wp = (const float*)d_in[16]; bp = (const float*)d_in[17];
        w1 = (const float*)d_in[18]; b1 = (const float*)d_in[19];
        w2 = (const float*)d_in[20]; b2 = (const float*)d_in[21];
    } else {
        wq = (const float*)d_in[8];  bq = (const float*)d_in[9];
        wk = (const float*)d_in[10]; bk = (const float*)d_in[11];
        wv = (const float*)d_in[12]; bv = (const float*)d_in[13];
        wp = (const float*)d_in[14]; bp = (const float*)d_in[15];
        ng = (const float*)d_in[16]; nb = (const float*)d_in[17];
        w1 = (const float*)d_in[18]; b1 = (const float*)d_in[19];
        w2 = (const float*)d_in[20]; b2 = (const float*)d_in[21];
    }
    float* out = (float*)d_out;

    float* sc = nullptr;
    cudaGetSymbolAddress((void**)&sc, g_scratch);
    __half* lnq = (__half*)(sc + 0 * SLAB);
    __half* lnk = (__half*)(sc + 1 * SLAB);
    __half* lnv = (__half*)(sc + 2 * SLAB);
    __half* q   = (__half*)(sc + 3 * SLAB);
    __half* k   = (__half*)(sc + 4 * SLAB);
    __half* vT  = (__half*)(sc + 5 * SLAB);
    __half* ao  = (__half*)(sc + 6 * SLAB);
    float*  hbuf= sc + 7 * SLAB;
    __half* lnh = (__half*)(sc + 8 * SLAB);
    __half* m1  = (__half*)(sc + 9 * SLAB);
    float*  wbase = sc + 9 * SLAB + (size_t)TOKENS * MLPH;
    __half* wqT = (__half*)(wbase);
    __half* wkT = (__half*)(wbase + WSZ);
    __half* wvT = (__half*)(wbase + 2 * WSZ);
    __half* wpT = (__half*)(wbase + 3 * WSZ);
    __half* w1T = (__half*)(wbase + 4 * WSZ);
    __half* w2T = (__half*)(wbase + 4 * WSZ + (size_t)CDIM * MLPH);

    cudaFuncSetAttribute(attn5_kernel,
                         cudaFuncAttributeMaxDynamicSharedMemorySize,
                         ATT4_SMEM_BYTES);

    transpose_kernel<<<dim3(CDIM / 32, CDIM / 32), 256>>>(wq, wqT, CDIM, CDIM);
    transpose_kernel<<<dim3(CDIM / 32, CDIM / 32), 256>>>(wk, wkT, CDIM, CDIM);
    transpose_kernel<<<dim3(CDIM / 32, CDIM / 32), 256>>>(wv, wvT, CDIM, CDIM);

    ln_qkv_kernel<<<TOKENS, 256>>>(x, pe, nqg, nqb, nkg, nkb, nvg, nvb,
                                   lnq, lnk, lnv);

    transpose_kernel<<<dim3(CDIM / 32, CDIM / 32), 256>>>(wp, wpT, CDIM, CDIM);

    dim3 gC(CDIM / 128, TOKENS / 128);
    gemm_fp16<0><<<gC, 256>>>(lnq, wqT, bq, nullptr, q, TOKENS, CDIM, CDIM);
    gemm_fp16<0><<<gC, 256>>>(lnk, wkT, bk, nullptr, k, TOKENS, CDIM, CDIM);
    gemm_fp16<3><<<gC, 256>>>(lnv, wvT, bv, nullptr, vT, TOKENS, CDIM, CDIM);

    transpose_kernel<<<dim3(MLPH / 32, CDIM / 32), 256>>>(w1, w1T, CDIM, MLPH);
    transpose_kernel<<<dim3(CDIM / 32, MLPH / 32), 256>>>(w2, w2T, MLPH, CDIM);

    dim3 gA(NSEQ / 128, 4 * NHEADS);
    attn5_kernel<<<gA, 256, ATT4_SMEM_BYTES>>>(q, k, vT, ao);

    gemm_fp16<2><<<gC, 256>>>(ao, wpT, bp, x, hbuf, TOKENS, CDIM, CDIM);

    ln_kernel<<<TOKENS, 256>>>(hbuf, ng, nb, lnh);

    dim3 gH(MLPH / 128, TOKENS / 128);
    gemm_fp16<1><<<gH, 256>>>(lnh, w1T, b1, nullptr, m1, TOKENS, MLPH, CDIM);

    gemm_fp16<2><<<gC, 256>>>(m1, w2T, b2, hbuf, out, TOKENS, CDIM, MLPH);
}